// round 15
// baseline (speedup 1.0000x reference)
#include <cuda_runtime.h>
#include <cuda_bf16.h>
#include <math.h>

#define BB   2
#define LSEQ 2048
#define DM   1024
#define DI   2048
#define NH   8
#define DH   128
#define NEXP 4
#define DFF  4096
#define NTOK (BB*LSEQ)   // 4096
#define NCH  16
#define CLEN 128         // LSEQ/NCH

typedef __nv_bfloat16 bf16;

// ---------------- static scratch ----------------
__device__ float g_xz[NTOK*2*DI];
__device__ float g_xc[NTOK*DI];
__device__ float g_dtBC[NTOK*64];
__device__ float g_scanp[NTOK*48];
__device__ float g_x1[NTOK*DM];
__device__ float g_x2[NTOK*DM];
__device__ float g_g1[NTOK*512];
__device__ float g_gs[NTOK*NEXP];
__device__ int   g_topi[NTOK*2];
__device__ float g_topw[NTOK*2];
__device__ int   g_cnt[NEXP];
__device__ int   g_slot[NTOK*2];
__device__ float g_hend[BB*NCH*DI*16];
__device__ float g_h0[BB*NCH*DI*16];
__device__ float g_P[BB*NCH*16];
__device__ float2 g_ropetab[LSEQ*64];

// bf16 activations
__device__ bf16 g_rms1b[NTOK*DM];
__device__ bf16 g_xcb[NTOK*DI];
__device__ bf16 g_ymulb[NTOK*DI];
__device__ bf16 g_rms2b[NTOK*DM];
__device__ bf16 g_qkvb[NTOK*3*DM];
__device__ bf16 g_qb[NTOK*DM];
__device__ bf16 g_kb[NTOK*DM];
__device__ bf16 g_vb[NTOK*DM];
__device__ bf16 g_attb[NTOK*DM];
__device__ bf16 g_xfb[NTOK*DM];
__device__ bf16 g_xgb[NEXP*NTOK*DM];
__device__ bf16 g_hb[(long)NEXP*NTOK*DFF];
__device__ bf16 g_eob[NEXP*NTOK*DM];

// bf16 weights
__device__ bf16 g_Winb[DM*2*DI];
__device__ bf16 g_Woutb[DI*DM];
__device__ bf16 g_Wqkvb[DM*3*DM];
__device__ bf16 g_Wob[DM*DM];
__device__ bf16 g_Wg1b[DM*512];
__device__ bf16 g_w12b[(long)NEXP*DM*2*DFF];
__device__ bf16 g_w3b[(long)NEXP*DFF*DM];
__device__ bf16 g_Wcatb[DI*64];

__device__ __forceinline__ float siluf(float x){ return x / (1.f + expf(-x)); }

// ---------------- rope table ----------------
__global__ void ropetab_k(float2* __restrict__ tab){
    int t = blockIdx.x;
    int j = threadIdx.x;   // 64
    const float lg = logf(10000.f) / 64.f;
    float inv = expf(-(float)j * lg);
    float ang = (float)t * inv;
    tab[t*64 + j] = make_float2(cosf(ang), sinf(ang));
}

// ---------------- merged fp32 -> bf16 conversions (6 segments) ----------------
__global__ void convall_k(const float* __restrict__ s0, bf16* __restrict__ d0, long n0,
                          const float* __restrict__ s1, bf16* __restrict__ d1, long n1,
                          const float* __restrict__ s2, bf16* __restrict__ d2, long n2,
                          const float* __restrict__ s3, bf16* __restrict__ d3, long n3,
                          const float* __restrict__ s4, bf16* __restrict__ d4, long n4,
                          const float* __restrict__ s5, bf16* __restrict__ d5, long n5){
    long i = ((long)blockIdx.x*blockDim.x + threadIdx.x)*4;
    const float* s; bf16* d;
    if (i < n0){ s = s0; d = d0; }
    else { i -= n0;
    if (i < n1){ s = s1; d = d1; }
    else { i -= n1;
    if (i < n2){ s = s2; d = d2; }
    else { i -= n2;
    if (i < n3){ s = s3; d = d3; }
    else { i -= n3;
    if (i < n4){ s = s4; d = d4; }
    else { i -= n4;
    if (i >= n5) return;
    s = s5; d = d5; }}}}}
    float4 v = *reinterpret_cast<const float4*>(s + i);
    *reinterpret_cast<__nv_bfloat162*>(d + i)     = __floats2bfloat162_rn(v.x, v.y);
    *reinterpret_cast<__nv_bfloat162*>(d + i + 2) = __floats2bfloat162_rn(v.z, v.w);
}

// pack w1|w2 INTERLEAVED
__global__ void pack12_k(const float* __restrict__ w1, const float* __restrict__ w2,
                         bf16* __restrict__ o){
    long i = ((long)blockIdx.x*blockDim.x + threadIdx.x)*4;
    if (i >= (long)NEXP*DM*DFF) return;
    long row = i >> 12;
    int  j   = (int)(i & 4095);
    float4 a = *reinterpret_cast<const float4*>(w1 + i);
    float4 b = *reinterpret_cast<const float4*>(w2 + i);
    bf16* d1 = o + row*(2*DFF) + 2*j;
    *reinterpret_cast<__nv_bfloat162*>(d1)   = __floats2bfloat162_rn(a.x, b.x);
    *reinterpret_cast<__nv_bfloat162*>(d1+2) = __floats2bfloat162_rn(a.y, b.y);
    *reinterpret_cast<__nv_bfloat162*>(d1+4) = __floats2bfloat162_rn(a.z, b.z);
    *reinterpret_cast<__nv_bfloat162*>(d1+6) = __floats2bfloat162_rn(a.w, b.w);
}

// pack [W_dt | W_B | W_C | 0] -> [2048][64] bf16
__global__ void packw_k(const float* __restrict__ Wdt, const float* __restrict__ WB,
                        const float* __restrict__ WC, bf16* __restrict__ o){
    int idx = blockIdx.x*256 + threadIdx.x;
    if (idx >= DI*64) return;
    int j = idx >> 6, n = idx & 63;
    float v = 0.f;
    if (n < 16) v = Wdt[j*16+n];
    else if (n < 32) v = WB[j*16+n-16];
    else if (n < 48) v = WC[j*16+n-32];
    o[idx] = __float2bfloat16(v);
}

// ---------------- RMSNorm -> bf16 (vectorized, warp reduce) ----------------
__global__ void rmsnorm_bf_k(const float* __restrict__ x, const float* __restrict__ w,
                             bf16* __restrict__ o){
    int row = blockIdx.x;
    int tid = threadIdx.x;
    const float* xr = x + (long)row*DM;
    float4 v = *reinterpret_cast<const float4*>(xr + tid*4);
    float s = v.x*v.x + v.y*v.y + v.z*v.z + v.w*v.w;
    #pragma unroll
    for (int off = 16; off > 0; off >>= 1)
        s += __shfl_xor_sync(0xffffffffu, s, off);
    __shared__ float red[8];
    if ((tid & 31) == 0) red[tid >> 5] = s;
    __syncthreads();
    float tot = red[0] + red[1] + red[2] + red[3]
              + red[4] + red[5] + red[6] + red[7];
    float r = rsqrtf(tot/(float)DM + 1e-6f);
    float4 wv = *reinterpret_cast<const float4*>(w + tid*4);
    bf16* ob = o + (long)row*DM + tid*4;
    *reinterpret_cast<__nv_bfloat162*>(ob)   = __floats2bfloat162_rn(wv.x*v.x*r, wv.y*v.y*r);
    *reinterpret_cast<__nv_bfloat162*>(ob+2) = __floats2bfloat162_rn(wv.z*v.z*r, wv.w*v.w*r);
}

// ---------------- MMA primitives ----------------
__device__ __forceinline__ void cpasync16(unsigned dst, const void* src, int ssz){
    asm volatile("cp.async.ca.shared.global [%0], [%1], 16, %2;"
        :: "r"(dst), "l"(src), "r"(ssz));
}
__device__ __forceinline__ void cp_commit(){ asm volatile("cp.async.commit_group;"); }
__device__ __forceinline__ void cp_wait0(){ asm volatile("cp.async.wait_group 0;"); }
__device__ __forceinline__ void cp_wait1(){ asm volatile("cp.async.wait_group 1;"); }
__device__ __forceinline__ void ldsm_x4(unsigned saddr, unsigned &o0, unsigned &o1,
                                        unsigned &o2, unsigned &o3){
    asm volatile("ldmatrix.sync.aligned.m8n8.x4.shared.b16 {%0,%1,%2,%3},[%4];"
        : "=r"(o0),"=r"(o1),"=r"(o2),"=r"(o3) : "r"(saddr));
}
__device__ __forceinline__ void ldsm_x4_t(unsigned saddr, unsigned &o0, unsigned &o1,
                                          unsigned &o2, unsigned &o3){
    asm volatile("ldmatrix.sync.aligned.m8n8.x4.trans.shared.b16 {%0,%1,%2,%3},[%4];"
        : "=r"(o0),"=r"(o1),"=r"(o2),"=r"(o3) : "r"(saddr));
}
__device__ __forceinline__ void mma16816(float* d, const unsigned* am, const unsigned* bm){
    asm volatile("mma.sync.aligned.m16n8k16.row.col.f32.bf16.bf16.f32 "
        "{%0,%1,%2,%3},{%4,%5,%6,%7},{%8,%9},{%0,%1,%2,%3};"
        : "+f"(d[0]),"+f"(d[1]),"+f"(d[2]),"+f"(d[3])
        : "r"(am[0]),"r"(am[1]),"r"(am[2]),"r"(am[3]), "r"(bm[0]),"r"(bm[1]));
}
__device__ __forceinline__ unsigned pkbf2(float x, float y){
    __nv_bfloat162 t = __floats2bfloat162_rn(x, y);
    return *reinterpret_cast<unsigned*>(&t);
}

// ---------------- 128x128 GEMM (fp32 out, no epilogue) ----------------
__device__ __forceinline__ void stage_tiles(const bf16* Ab, const bf16* Bb,
    int bm, int bn, int N, int lda, int ldb, int k0, int tid,
    unsigned Adst, unsigned Bdst)
{
    #pragma unroll
    for (int c = tid; c < 512; c += 256){
        int r  = c >> 2;
        int ko = (c & 3) << 3;
        cpasync16(Adst + 2u*(unsigned)(r*40 + ko),
                  Ab + (long)(bm + r)*lda + k0 + ko, 16);
    }
    #pragma unroll
    for (int c = tid; c < 512; c += 256){
        int r  = c >> 4;
        int no = (c & 15) << 3;
        const bf16* src = Bb + (long)(k0 + r)*ldb + bn + no;
        int ssz = 16;
        if (bn + no >= N){ src = Bb; ssz = 0; }
        cpasync16(Bdst + 2u*(unsigned)(r*136 + no), src, ssz);
    }
}

__global__ void __launch_bounds__(256) bgemm_k(
    const bf16* __restrict__ Aptr, const bf16* __restrict__ Bptr, float* __restrict__ Cv,
    int M, int N, int K, int lda, int ldb, int ldc)
{
    __shared__ bf16 As[3*5120];
    __shared__ bf16 Bs[3*5120];
    const int bm = blockIdx.y * 128;
    const int bn = blockIdx.x * 128;
    const int tid  = threadIdx.x;
    const int lane = tid & 31;
    const int warp = tid >> 5;
    const int wm = warp >> 1;
    const int wn = warp & 1;

    float acc[2][8][4];
    #pragma unroll
    for (int i = 0; i < 2; i++)
        #pragma unroll
        for (int j = 0; j < 8; j++)
            #pragma unroll
            for (int q = 0; q < 4; q++) acc[i][j][q] = 0.f;

    unsigned Afrag[2][4];
    unsigned Bfrag[8][2];

    const unsigned As_base = (unsigned)__cvta_generic_to_shared(As);
    const unsigned Bs_base = (unsigned)__cvta_generic_to_shared(Bs);

    const int rowA = wm*32 + (lane & 15);
    const int colA = (lane >> 4) * 8;
    unsigned aoff0 = As_base + 2u*(unsigned)( rowA       *40 + colA);
    unsigned aoff1 = As_base + 2u*(unsigned)((rowA + 16) *40 + colA);

    unsigned boff[4];
    #pragma unroll
    for (int p = 0; p < 4; p++){
        int brow = lane & 15;
        int bcol = (lane >> 4) * 8;
        boff[p] = Bs_base + 2u*(unsigned)(brow*136 + wn*64 + p*16 + bcol);
    }

    const int nk = K >> 5;
    stage_tiles(Aptr, Bptr, bm, bn, N, lda, ldb, 0, tid, As_base, Bs_base);
    cp_commit();
    if (nk > 1){
        stage_tiles(Aptr, Bptr, bm, bn, N, lda, ldb, 32, tid,
                    As_base + 10240u, Bs_base + 10240u);
        cp_commit();
    }

    unsigned sb = 0u;
    for (int it = 0; it < nk; it++){
        if (it + 1 < nk) cp_wait1(); else cp_wait0();
        __syncthreads();
        if (it + 2 < nk){
            unsigned off = (unsigned)((it + 2) % 3) * 10240u;
            stage_tiles(Aptr, Bptr, bm, bn, N, lda, ldb, (it+2) << 5, tid,
                        As_base + off, Bs_base + off);
            cp_commit();
        }
        #pragma unroll
        for (int ks = 0; ks < 32; ks += 16){
            ldsm_x4(aoff0 + sb + 2u*ks, Afrag[0][0], Afrag[0][1], Afrag[0][2], Afrag[0][3]);
            ldsm_x4(aoff1 + sb + 2u*ks, Afrag[1][0], Afrag[1][1], Afrag[1][2], Afrag[1][3]);
            #pragma unroll
            for (int p = 0; p < 4; p++){
                unsigned ba = boff[p] + sb + 2u*(unsigned)(ks*136);
                ldsm_x4_t(ba, Bfrag[2*p][0], Bfrag[2*p][1],
                              Bfrag[2*p+1][0], Bfrag[2*p+1][1]);
            }
            #pragma unroll
            for (int mt = 0; mt < 2; mt++)
                #pragma unroll
                for (int nt = 0; nt < 8; nt++)
                    mma16816(acc[mt][nt], Afrag[mt], Bfrag[nt]);
        }
        sb += 10240u;
        if (sb == 30720u) sb = 0u;
    }

    #pragma unroll
    for (int mt = 0; mt < 2; mt++){
        int r0 = bm + wm*32 + mt*16 + (lane >> 2);
        #pragma unroll
        for (int nt = 0; nt < 8; nt++){
            int col = bn + wn*64 + nt*8 + ((lane & 3) << 1);
            if (col < N){
                *reinterpret_cast<float2*>(&Cv[(long)r0*ldc + col]) =
                    make_float2(acc[mt][nt][0], acc[mt][nt][1]);
                *reinterpret_cast<float2*>(&Cv[(long)(r0+8)*ldc + col]) =
                    make_float2(acc[mt][nt][2], acc[mt][nt][3]);
            }
        }
    }
}

// ---------------- 256x128 GEMM, 3 slots x 64-K groups, dynamic smem ----------------
#define GSLOT_A 40960u
#define GSLOT_B 17408u
#define DSMEM256 (3*(GSLOT_A + GSLOT_B))

__device__ __forceinline__ void stage256(const bf16* Ab, const bf16* Bb,
    int bm, int bn, int N, int lda, int ldb, int k0, int tid,
    unsigned Adst, unsigned Bdst)
{
    #pragma unroll
    for (int c = tid; c < 1024; c += 256){
        int r  = c >> 2;
        int ko = (c & 3) << 3;
        cpasync16(Adst + 2u*(unsigned)(r*40 + ko),
                  Ab + (long)(bm + r)*lda + k0 + ko, 16);
    }
    #pragma unroll
    for (int c = tid; c < 512; c += 256){
        int r  = c >> 4;
        int no = (c & 15) << 3;
        const bf16* src = Bb + (long)(k0 + r)*ldb + bn + no;
        int ssz = 16;
        if (bn + no >= N){ src = Bb; ssz = 0; }
        cpasync16(Bdst + 2u*(unsigned)(r*136 + no), src, ssz);
    }
}

// EPI: 0 none, 1 relu(acc+bias) fp32, 2 resid fp32, 3 siluGLU bf16
template<int EPI, int OUTBF>
__global__ void __launch_bounds__(256) bgemm256_k(
    const bf16* __restrict__ Aptr, const bf16* __restrict__ Bptr, void* __restrict__ Cv,
    int M, int N, int K, int lda, int ldb, int ldc,
    long sA, long sB, long sC, const float* __restrict__ bias,
    const float* __restrict__ resx, const int* __restrict__ mcnt)
{
    extern __shared__ bf16 dsm[];
    const int bm = blockIdx.y * 256;
    int Meff = M;
    if (mcnt) Meff = mcnt[blockIdx.z];
    if (bm >= Meff) return;
    const bf16* Ab = Aptr + (long)blockIdx.z * sA;
    const bf16* Bb = Bptr + (long)blockIdx.z * sB;
    const int bn = blockIdx.x * 128;
    const int tid  = threadIdx.x;
    const int lane = tid & 31;
    const int warp = tid >> 5;
    const int wm = warp >> 1;
    const int wn = warp & 1;

    float acc[4][8][4];
    #pragma unroll
    for (int i = 0; i < 4; i++)
        #pragma unroll
        for (int j = 0; j < 8; j++)
            #pragma unroll
            for (int q = 0; q < 4; q++) acc[i][j][q] = 0.f;

    unsigned Afrag[4][4];
    unsigned Bfrag[8][2];

    const unsigned As_base = (unsigned)__cvta_generic_to_shared(dsm);
    const unsigned Bs_base = As_base + 3u*GSLOT_A;

    const int rowA = wm*64 + (lane & 15);
    const int colA = (lane >> 4) * 8;
    unsigned aoff[4];
    #pragma unroll
    for (int mt = 0; mt < 4; mt++)
        aoff[mt] = As_base + 2u*(unsigned)((rowA + mt*16)*40 + colA);

    unsigned boff[4];
    {
        int brow = lane & 15;
        int bcol = (lane >> 4) * 8;
        #pragma unroll
        for (int p = 0; p < 4; p++)
            boff[p] = Bs_base + 2u*(unsigned)(brow*136 + wn*64 + p*16 + bcol);
    }

    const int ng = K >> 6;
    stage256(Ab, Bb, bm, bn, N, lda, ldb, 0,  tid, As_base,           Bs_base);
    stage256(Ab, Bb, bm, bn, N, lda, ldb, 32, tid, As_base + 20480u,  Bs_base + 8704u);
    cp_commit();
    if (ng > 1){
        stage256(Ab, Bb, bm, bn, N, lda, ldb, 64, tid, As_base + GSLOT_A,           Bs_base + GSLOT_B);
        stage256(Ab, Bb, bm, bn, N, lda, ldb, 96, tid, As_base + GSLOT_A + 20480u,  Bs_base + GSLOT_B + 8704u);
        cp_commit();
    }

    for (int g = 0; g < ng; g++){
        if (g + 1 < ng) cp_wait1(); else cp_wait0();
        __syncthreads();
        if (g + 2 < ng){
            unsigned sl = (unsigned)((g + 2) % 3);
            int k0 = (g + 2) << 6;
            stage256(Ab, Bb, bm, bn, N, lda, ldb, k0,      tid,
                     As_base + sl*GSLOT_A,           Bs_base + sl*GSLOT_B);
            stage256(Ab, Bb, bm, bn, N, lda, ldb, k0 + 32, tid,
                     As_base + sl*GSLOT_A + 20480u,  Bs_base + sl*GSLOT_B + 8704u);
            cp_commit();
        }
        unsigned slA = (unsigned)(g % 3) * GSLOT_A;
        unsigned slB = (unsigned)(g % 3) * GSLOT_B;
        #pragma unroll
        for (int sub = 0; sub < 2; sub++){
            unsigned sa  = slA + (unsigned)sub*20480u;
            unsigned sbb = slB + (unsigned)sub*8704u;
            #pragma unroll
            for (int ks = 0; ks < 32; ks += 16){
                #pragma unroll
                for (int mt = 0; mt < 4; mt++)
                    ldsm_x4(aoff[mt] + sa + 2u*ks,
                            Afrag[mt][0], Afrag[mt][1], Afrag[mt][2], Afrag[mt][3]);
                #pragma unroll
                for (int p = 0; p < 4; p++){
                    unsigned ba = boff[p] + sbb + 2u*(unsigned)(ks*136);
                    ldsm_x4_t(ba, Bfrag[2*p][0], Bfrag[2*p][1],
                                  Bfrag[2*p+1][0], Bfrag[2*p+1][1]);
                }
                #pragma unroll
                for (int mt = 0; mt < 4; mt++)
                    #pragma unroll
                    for (int nt = 0; nt < 8; nt++)
                        mma16816(acc[mt][nt], Afrag[mt], Bfrag[nt]);
            }
        }
    }

    #pragma unroll
    for (int mt = 0; mt < 4; mt++){
        int r0 = bm + wm*64 + mt*16 + (lane >> 2);
        #pragma unroll
        for (int nt = 0; nt < 8; nt++){
            int col = bn + wn*64 + nt*8 + ((lane & 3) << 1);
            if (col < N){
                float v0 = acc[mt][nt][0];
                float v1 = acc[mt][nt][1];
                float v2 = acc[mt][nt][2];
                float v3 = acc[mt][nt][3];
                if (EPI == 3){
                    bf16* Cb = (bf16*)Cv + (long)blockIdx.z * sC;
                    int jc = col >> 1;
                    Cb[(long)r0*(N>>1) + jc]     = __float2bfloat16(siluf(v0)*v1);
                    Cb[(long)(r0+8)*(N>>1) + jc] = __float2bfloat16(siluf(v2)*v3);
                    continue;
                }
                if (EPI == 1){
                    float b0 = bias[col];
                    float b1 = bias[col+1];
                    v0 = fmaxf(v0+b0, 0.f); v1 = fmaxf(v1+b1, 0.f);
                    v2 = fmaxf(v2+b0, 0.f); v3 = fmaxf(v3+b1, 0.f);
                }
                if (EPI == 2){
                    float b0 = bias[col];
                    float b1 = bias[col+1];
                    v0 = fmaf(b0, v0, resx[(long)r0*ldc + col]);
                    v1 = fmaf(b1, v1, resx[(long)r0*ldc + col + 1]);
                    v2 = fmaf(b0, v2, resx[(long)(r0+8)*ldc + col]);
                    v3 = fmaf(b1, v3, resx[(long)(r0+8)*ldc + col + 1]);
                }
                if (OUTBF){
                    bf16* Cb = (bf16*)Cv + (long)blockIdx.z * sC;
                    *reinterpret_cast<__nv_bfloat162*>(&Cb[(long)r0*ldc + col]) =
                        __floats2bfloat162_rn(v0, v1);
                    *reinterpret_cast<__nv_bfloat162*>(&Cb[(long)(r0+8)*ldc + col]) =
                        __floats2bfloat162_rn(v2, v3);
                } else {
                    float* Cb = (float*)Cv + (long)blockIdx.z * sC;
                    *reinterpret_cast<float2*>(&Cb[(long)r0*ldc + col]) = make_float2(v0, v1);
                    *reinterpret_cast<float2*>(&Cb[(long)(r0+8)*ldc + col]) = make_float2(v2, v3);
                }
            }
        }
    }
}

// ---------------- fused flash attention ----------------
#define FTILE (128*136)
#define FSMEM (5*FTILE*2)

__device__ __forceinline__ void fstage(const bf16* src, unsigned dst, int tid){
    for (int i = tid; i < 2048; i += 256){
        int r = i >> 4, c = (i & 15) << 3;
        cpasync16(dst + 2u*(unsigned)(r*136 + c), src + r*DH + c, 16);
    }
}

__global__ void __launch_bounds__(256, 1) flash_k(
    const bf16* __restrict__ q, const bf16* __restrict__ k, const bf16* __restrict__ v,
    const float* __restrict__ ascale, bf16* __restrict__ att)
{
    extern __shared__ bf16 fs[];
    const int qt = blockIdx.x, bh = blockIdx.y;
    const int bb = bh >> 3, hh = bh & 7;
    const int tid = threadIdx.x, lane = tid & 31, w = tid >> 5;
    const float a = ascale[hh];

    const bf16* qg = q + ((long)bh*LSEQ + qt*128)*DH;
    const bf16* kg = k + (long)bh*LSEQ*DH;
    const bf16* vg = v + (long)bh*LSEQ*DH;

    const unsigned Qb = (unsigned)__cvta_generic_to_shared(fs);
    const unsigned Kb = Qb + 2u*FTILE;
    const unsigned Vb = Qb + 6u*FTILE;
    const unsigned TILEB = 2u*FTILE;

    fstage(qg, Qb, tid);
    fstage(kg, Kb, tid);
    fstage(vg, Vb, tid);
    cp_commit();
    cp_wait0();
    __syncthreads();

    unsigned qf[8][4];
    {
        int rq = w*16 + (lane & 15);
        int cq = (lane >> 4) << 3;
        #pragma unroll
        for (int ks = 0; ks < 8; ks++)
            ldsm_x4(Qb + 2u*(unsigned)(rq*136 + ks*16 + cq),
                    qf[ks][0], qf[ks][1], qf[ks][2], qf[ks][3]);
    }

    const int brow = (lane & 7) + (((lane >> 4) & 1) << 3);
    const int bcol = ((lane >> 3) & 1) << 3;
    unsigned kadr[8], vadr[8];
    #pragma unroll
    for (int p = 0; p < 8; p++){
        kadr[p] = Kb + 2u*(unsigned)((p*16 + brow)*136 + bcol);
        vadr[p] = Vb + 2u*(unsigned)((lane & 15)*136 + p*16 + ((lane >> 4) << 3));
    }

    float oacc[16][4];
    #pragma unroll
    for (int nt = 0; nt < 16; nt++)
        #pragma unroll
        for (int qq = 0; qq < 4; qq++) oacc[nt][qq] = 0.f;
    float m0 = -1e30f, m1 = -1e30f, l0 = 0.f, l1 = 0.f;

    for (int kt = 0; kt < 16; kt++){
        if (kt > 0){ cp_wait0(); __syncthreads(); }
        if (kt + 1 < 16){
            unsigned off = ((kt + 1) & 1) ? TILEB : 0u;
            fstage(kg + (long)(kt+1)*128*DH, Kb + off, tid);
            fstage(vg + (long)(kt+1)*128*DH, Vb + off, tid);
            cp_commit();
        }
        const unsigned sb = (kt & 1) ? TILEB : 0u;

        float sacc[16][4];
        #pragma unroll
        for (int nt = 0; nt < 16; nt++)
            #pragma unroll
            for (int qq = 0; qq < 4; qq++) sacc[nt][qq] = 0.f;

        #pragma unroll
        for (int ks = 0; ks < 8; ks++){
            #pragma unroll
            for (int p = 0; p < 8; p++){
                unsigned bf0[2], bf1[2];
                ldsm_x4(kadr[p] + sb + 2u*(unsigned)(ks*16),
                        bf0[0], bf0[1], bf1[0], bf1[1]);
                mma16816(sacc[2*p],   qf[ks], bf0);
                mma16816(sacc[2*p+1], qf[ks], bf1);
            }
        }

        float ax0 = -1e30f, ax1 = -1e30f;
        #pragma unroll
        for (int nt = 0; nt < 16; nt++){
            sacc[nt][0] *= a; sacc[nt][1] *= a; sacc[nt][2] *= a; sacc[nt][3] *= a;
            ax0 = fmaxf(ax0, fmaxf(sacc[nt][0], sacc[nt][1]));
            ax1 = fmaxf(ax1, fmaxf(sacc[nt][2], sacc[nt][3]));
        }
        ax0 = fmaxf(ax0, __shfl_xor_sync(0xffffffffu, ax0, 1));
        ax0 = fmaxf(ax0, __shfl_xor_sync(0xffffffffu, ax0, 2));
        ax1 = fmaxf(ax1, __shfl_xor_sync(0xffffffffu, ax1, 1));
        ax1 = fmaxf(ax1, __shfl_xor_sync(0xffffffffu, ax1, 2));
        float mn0 = fmaxf(m0, ax0), mn1 = fmaxf(m1, ax1);
        float f0 = expf(m0 - mn0), f1 = expf(m1 - mn1);

        float rs0 = 0.f, rs1 = 0.f;
        #pragma unroll
        for (int nt = 0; nt < 16; nt++){
            sacc[nt][0] = expf(sacc[nt][0] - mn0);
            sacc[nt][1] = expf(sacc[nt][1] - mn0);
            sacc[nt][2] = expf(sacc[nt][2] - mn1);
            sacc[nt][3] = expf(sacc[nt][3] - mn1);
            rs0 += sacc[nt][0] + sacc[nt][1];
            rs1 += sacc[nt][2] + sacc[nt][3];
        }
        rs0 += __shfl_xor_sync(0xffffffffu, rs0, 1);
        rs0 += __shfl_xor_sync(0xffffffffu, rs0, 2);
        rs1 += __shfl_xor_sync(0xffffffffu, rs1, 1);
        rs1 += __shfl_xor_sync(0xffffffffu, rs1, 2);
        l0 = l0*f0 + rs0; l1 = l1*f1 + rs1;
        m0 = mn0; m1 = mn1;

        #pragma unroll
        for (int nt = 0; nt < 16; nt++){
            oacc[nt][0] *= f0; oacc[nt][1] *= f0;
            oacc[nt][2] *= f1; oacc[nt][3] *= f1;
        }

        unsigned pa[8][4];
        #pragma unroll
        for (int ksp = 0; ksp < 8; ksp++){
            pa[ksp][0] = pkbf2(sacc[2*ksp][0],   sacc[2*ksp][1]);
            pa[ksp][1] = pkbf2(sacc[2*ksp][2],   sacc[2*ksp][3]);
            pa[ksp][2] = pkbf2(sacc[2*ksp+1][0], sacc[2*ksp+1][1]);
            pa[ksp][3] = pkbf2(sacc[2*ksp+1][2], sacc[2*ksp+1][3]);
        }

        #pragma unroll
        for (int ksp = 0; ksp < 8; ksp++){
            #pragma unroll
            for (int p = 0; p < 8; p++){
                unsigned bf0[2], bf1[2];
                ldsm_x4_t(vadr[p] + sb + 2u*(unsigned)(ksp*16*136),
                          bf0[0], bf0[1], bf1[0], bf1[1]);
                mma16816(oacc[2*p],   pa[ksp], bf0);
                mma16816(oacc[2*p+1], pa[ksp], bf1);
            }
        }
    }

    float inv0 = 1.f / l0, inv1 = 1.f / l1;
    long row0 = (long)bb*LSEQ + qt*128 + w*16 + (lane >> 2);
    long row1 = row0 + 8;
    int  cbase = hh*DH + ((lane & 3) << 1);
    #pragma unroll
    for (int nt = 0; nt < 16; nt++){
        int col = cbase + nt*8;
        *reinterpret_cast<__nv_bfloat162*>(&att[row0*DM + col]) =
            __floats2bfloat162_rn(oacc[nt][0]*inv0, oacc[nt][1]*inv0);
        *reinterpret_cast<__nv_bfloat162*>(&att[row1*DM + col]) =
            __floats2bfloat162_rn(oacc[nt][2]*inv1, oacc[nt][3]*inv1);
    }
}

// ---------------- depthwise conv + bias + SiLU (4-wide vectorized) ----------------
__global__ void conv_k(const float* __restrict__ xz, const float* __restrict__ cw,
                       const float* __restrict__ cb, float* __restrict__ xc,
                       bf16* __restrict__ xcb){
    long idx4 = (long)blockIdx.x*blockDim.x + threadIdx.x;
    if (idx4 >= (long)NTOK*DI/4) return;
    long idx = idx4 * 4;
    int d = (int)(idx % DI);
    int row = (int)(idx / DI);
    int t = row % LSEQ, b = row / LSEQ;
    float4 s = *reinterpret_cast<const float4*>(cb + d);
    float4 w0 = *reinterpret_cast<const float4*>(cw + d*4);
    float4 w1 = *reinterpret_cast<const float4*>(cw + (d+1)*4);
    float4 w2 = *reinterpret_cast<const float4*>(cw + (d+2)*4);
    float4 w3 = *reinterpret_cast<const float4*>(cw + (d+3)*4);
    const float* base = xz + (long)(b*LSEQ)*(2*DI) + d;
    #pragma unroll
    for (int k = 0; k < 4; k++){
        int tt = t + k - 2;
        if (tt >= 0 && tt < LSEQ){
            float4 xv = *reinterpret_cast<const float4*>(base + (long)tt*(2*DI));
            float wk0 = (k==0)?w0.x:(k==1)?w0.y:(k==2)?w0.z:w0.w;
            float wk1 = (k==0)?w1.x:(k==1)?w1.y:(k==2)?w1.z:w1.w;
            float wk2 = (k==0)?w2.x:(k==1)?w2.y:(k==2)?w2.z:w2.w;
            float wk3 = (k==0)?w3.x:(k==1)?w3.y:(k==2)?w3.z:w3.w;
            s.x = fmaf(wk0, xv.x, s.x);
            s.y = fmaf(wk1, xv.y, s.y);
            s.z = fmaf(wk2, xv.z, s.z);
            s.w = fmaf(wk3, xv.w, s.w);
        }
    }
    float4 v = make_float4(siluf(s.x), siluf(s.y), siluf(s.z), siluf(s.w));
    *reinterpret_cast<float4*>(xc + idx) = v;
    *reinterpret_cast<__nv_bfloat162*>(xcb + idx)     = __floats2bfloat162_rn(v.x, v.y);
    *reinterpret_cast<__nv_bfloat162*>(xcb + idx + 2) = __floats2bfloat162_rn(v.z, v.w);
}

// ---------------- scan preprocessing ----------------
__global__ void scanprep_k(const float* __restrict__ dtBC, const float* __restrict__ bdt,
                           const float* __restrict__ A, float* __restrict__ sp){
    int idx = blockIdx.x*blockDim.x + threadIdx.x;
    if (idx >= NTOK*16) return;
    int n = idx & 15, row = idx >> 4;
    float dtp = dtBC[(long)row*64 + n] + bdt[n];
    float dt  = fmaxf(dtp, 0.f) + log1pf(expf(-fabsf(dtp)));
    sp[(long)row*48 + n]      = expf(dt * A[n]);
    sp[(long)row*48 + 16 + n] = dt * dtBC[(long)row*64 + 16 + n];
    sp[(long)row*48 + 32 + n] = dtBC[(long)row*64 + 32 + n];
}

// ---------------- chunked selective scan (P folded into A) ----------------
__global__ void scanA_k(const float* __restrict__ sp, const float* __restrict__ xc,
                        float* __restrict__ hend, float* __restrict__ P){
    int b = blockIdx.z, ch = blockIdx.y;
    int d = blockIdx.x*128 + threadIdx.x;
    __shared__ float s[CLEN*48];
    const float* src = sp + ((long)b*LSEQ + ch*CLEN)*48;
    for (int i = threadIdx.x; i < CLEN*48; i += 128) s[i] = src[i];
    __syncthreads();
    // block 0 of each (b,ch): threads 0-15 compute chunk decay product
    if (blockIdx.x == 0 && threadIdx.x < 16){
        int n = threadIdx.x;
        float p = 1.f;
        for (int t = 0; t < CLEN; t++) p *= s[t*48 + n];
        P[(b*NCH + ch)*16 + n] = p;
    }
    float h[16];
    #pragma unroll
    for (int n = 0; n < 16; n++) h[n] = 0.f;
    long rowbase = (long)b*LSEQ + ch*CLEN;
    float xv_next = xc[rowbase*DI + d];
    for (int tt = 0; tt < CLEN; tt++){
        float xv = xv_next;
        if (tt + 1 < CLEN) xv_next = xc[(rowbase + tt + 1)*DI + d];
        const float* e = s + tt*48;
        #pragma unroll
        for (int n = 0; n < 16; n++)
            h[n] = fmaf(e[n], h[n], e[16+n]*xv);
    }
    float* o = hend + (((long)(b*NCH + ch)*DI + d) << 4);
    #pragma unroll
    for (int n = 0; n < 16; n += 4)
        *reinterpret_cast<float4*>(o + n) = make_float4(h[n], h[n+1], h[n+2], h[n+3]);
}

__global__ void scanComb_k(const float* __restrict__ hend, const float* __restrict__ P,
                           float* __restrict__ h0){
    int g = blockIdx.x*128 + threadIdx.x;
    int b = g / DI, d = g % DI;
    __shared__ float sP[NCH*16];
    for (int i = threadIdx.x; i < NCH*16; i += 128) sP[i] = P[b*NCH*16 + i];
    __syncthreads();
    float h[16];
    #pragma unroll
    for (int n = 0; n < 16; n++) h[n] = 0.f;
    {
        float* o = h0 + (((long)(b*NCH)*DI + d) << 4);
        #pragma unroll
        for (int n = 0; n < 16; n += 4)
            *reinterpret_cast<float4*>(o + n) = make_float4(0.f, 0.f, 0.f, 0.f);
    }
    for (int c = 1; c < NCH; c++){
        const float* he = hend + (((long)(b*NCH + c - 1)*DI + d) << 4);
        #pragma unroll
        for (int n = 0; n < 16; n++)
            h[n] = fmaf(sP[(c-1)*16 + n], h[n], he[n]);
        float* o = h0 + (((long)(b*NCH + c)*DI + d) << 4);
        #pragma unroll
        for (int n = 0; n < 16; n += 4)
            *reinterpret_cast<float4*>(o + n) = make_float4(h[n], h[n+1], h[n+2], h[n+3]);
    }
}

__global__ void scanC_k(const float* __restrict__ sp, const float* __restrict__ xc,
                        const float* __restrict__ xz, const float* __restrict__ Dp,
                        const float* __restrict__ h0, bf16* __restrict__ ymulb){
    int b = blockIdx.z, ch = blockIdx.y;
    int d = blockIdx.x*128 + threadIdx.x;
    __shared__ float s[CLEN*48];
    const float* src = sp + ((long)b*LSEQ + ch*CLEN)*48;
    for (int i = threadIdx.x; i < CLEN*48; i += 128) s[i] = src[i];
    __syncthreads();
    float h[16];
    {   const float* hi = h0 + (((long)(b*NCH + ch)*DI + d) << 4);
        #pragma unroll
        for (int n = 0; n < 16; n += 4){
            float4 v = *reinterpret_cast<const float4*>(hi + n);
            h[n] = v.x; h[n+1] = v.y; h[n+2] = v.z; h[n+3] = v.w;
        }
    }
    const float dpv = Dp[d];
    long rowbase = (long)b*LSEQ + ch*CLEN;
    float xv_next = xc[rowbase*DI + d];
    float z_next  = xz[rowbase*(2*DI) + DI + d];
    for (int tt = 0; tt < CLEN; tt++){
        float xv = xv_next;
        float z  = z_next;
        if (tt + 1 < CLEN){
            xv_next = xc[(rowbase + tt + 1)*DI + d];
            z_next  = xz[(rowbase + tt + 1)*(2*DI) + DI + d];
        }
        const float* e = s + tt*48;
        float y = 0.f;
        #pragma unroll
        for (int n = 0; n < 16; n++){
            h[n] = fmaf(e[n], h[n], e[16+n]*xv);
            y = fmaf(h[n], e[32+n], y);
        }
        ymulb[(rowbase + tt)*DI + d] = __float2bfloat16((y + dpv*xv) * siluf(z));
    }
}

// ---------------- RoPE (bf16 qkv in, table) -> qb,kb,vb bf16 ----------------
__global__ void rope2_k(const bf16* __restrict__ qkv, const float2* __restrict__ tab,
                        bf16* __restrict__ qb, bf16* __restrict__ kb, bf16* __restrict__ vb){
    int row = blockIdx.x;
    int t = row % LSEQ, b = row / LSEQ;
    __shared__ float q[DM], kk[DM];
    const bf16* base = qkv + (long)row*3*DM;
    for (int i = threadIdx.x; i < DM; i += 256){
        q[i]  = __bfloat162float(base[i]);
        kk[i] = __bfloat162float(base[DM+i]);
    }
    __syncthreads();
    const float sq = sqrtf((float)DH);
    const float2* trow = tab + t*64;
    for (int idx = threadIdx.x; idx < DM; idx += 256){
        int h = idx / DH, i = idx % DH;
        int j = i & 63;
        float2 cs = trow[j];
        float c = cs.x, s = cs.y;
        int off = h * DH;
        float rq, rk;
        if (i < 64){ rq = -q[off + 2*i + 1]; rk = -kk[off + 2*i + 1]; }
        else       { rq =  q[off + 2*(i-64)]; rk =  kk[off + 2*(i-64)]; }
        long o = ((long)(b*NH + h)*LSEQ + t)*DH + i;
        qb[o] = __float2bfloat16((q[idx]*c + rq*s) * sq);
        kb[o] = __float2bfloat16(kk[idx]*c + rk*s);
        vb[o] = base[2*DM + idx];
    }
}

// ---------------- gate stage 2 (bias+relu folded in; zeroes counters) ----------------
__global__ void gate2_k(const float* __restrict__ g1, const float* __restrict__ bg1,
                        const float* __restrict__ Wg2,
                        float* __restrict__ gs, int* __restrict__ topi, float* __restrict__ topw,
                        int* __restrict__ cnt){
    int row = blockIdx.x;
    int tid = threadIdx.x;
    if (row == 0 && tid < NEXP) cnt[tid] = 0;
    __shared__ float red[64*4];
    float a[4] = {0.f,0.f,0.f,0.f};
    for (int j = tid; j < 512; j += 64){
        float v = fmaxf(g1[(long)row*512 + j] + bg1[j], 0.f);
        #pragma unroll
        for (int e = 0; e < 4; e++) a[e] = fmaf(v, Wg2[j*4+e], a[e]);
    }
    #pragma unroll
    for (int e = 0; e < 4; e++) red[e*64 + tid] = a[e];
    __syncthreads();
    for (int st = 32; st > 0; st >>= 1){
        if (tid < st){
            #pragma unroll
            for (int e = 0; e < 4; e++) red[e*64+tid] += red[e*64+tid+st];
        }
        __syncthreads();
    }
    if (tid == 0){
        float l[4]; for (int e = 0; e < 4; e++) l[e] = red[e*64];
        float m = fmaxf(fmaxf(l[0],l[1]), fmaxf(l[2],l[3]));
        float ex[4]; float s = 0.f;
        for (int e = 0; e < 4; e++){ ex[e] = expf(l[e]-m); s += ex[e]; }
        float gsv[4];
        for (int e = 0; e < 4; e++){ gsv[e] = ex[e]/s; gs[(long)row*4+e] = gsv[e]; }
        int i0 = 0;
        for (int e = 1; e < 4; e++) if (gsv[e] > gsv[i0]) i0 = e;
        int i1 = -1;
        for (int e = 0; e < 4; e++) if (e != i0 && (i1 < 0 || gsv[e] > gsv[i1])) i1 = e;
        float v0 = gsv[i0], v1 = gsv[i1];
        float mm = fmaxf(v0, v1);
        float w0 = expf(v0-mm), w1 = expf(v1-mm);
        float ws = w0 + w1;
        topi[row*2] = i0; topi[row*2+1] = i1;
        topw[row*2] = w0/ws; topw[row*2+1] = w1/ws;
    }
}

// ---------------- balance loss ----------------
__global__ void bal_k(const float* __restrict__ gs, float* __restrict__ out){
    int tid = threadIdx.x;
    __shared__ float red[256*4];
    float a[4] = {0.f,0.f,0.f,0.f};
    for (int r = tid; r < NTOK; r += 256){
        #pragma unroll
        for (int e = 0; e < 4; e++) a[e] += gs[(long)r*4+e];
    }
    #pragma unroll
    for (int e = 0; e < 4; e++) red[e*256+tid] = a[e];
    __syncthreads();
    for (int st = 128; st > 0; st >>= 1){
        if (tid < st){
            #pragma unroll
            for (int e = 0; e < 4; e++) red[e*256+tid] += red[e*256+tid+st];
        }
        __syncthreads();
    }
    if (tid == 0){
        float bal = 0.f;
        for (int e = 0; e < 4; e++){
            float gm = red[e*256] / (float)NTOK;
            bal += gm * logf(gm + 1e-8f);
        }
        out[0] = (float)NEXP * bal;
    }
}

// ---------------- MoE routing ----------------
__global__ void assign_k(const int* __restrict__ topi, int* __restrict__ cnt,
                         int* __restrict__ slot){
    int idx = blockIdx.x*256 + threadIdx.x;
    if (idx >= NTOK*2) return;
    int e = topi[idx];
    int s = atomicAdd(&cnt[e], 1);
    slot[idx] = e*NTOK + s;
}

__global__ void gather_k(const bf16* __restrict__ xf, const int* __restrict__ slot,
                         bf16* __restrict__ xg){
    int idx = blockIdx.x;
    int tok = idx >> 1;
    int dst = slot[idx];
    const unsigned* src = reinterpret_cast<const unsigned*>(xf) + (long)tok*(DM/2);
    unsigned* d = reinterpret_cast<unsigned*>(xg) + (long)dst*(DM/2);
    for (int i = threadIdx.x; i < DM/2; i += 128) d[i] = src[i];
}

// ---------------- MoE combine + final residual ----------------
__global__ void combine2_k(const float* __restrict__ x2, const float* __restrict__ ls3,
                           const bf16* __restrict__ eo, const int* __restrict__ slot,
                           const float* __restrict__ topw, float* __restrict__ out){
    long idx = (long)blockIdx.x*blockDim.x + threadIdx.x;
    if (idx >= (long)NTOK*DM) return;
    int row = (int)(idx / DM), d = (int)(idx % DM);
    int s0 = slot[row*2], s1 = slot[row*2+1];
    float m = topw[row*2]   * __bfloat162float(eo[(long)s0*DM + d])
            + topw[row*2+1] * __bfloat162float(eo[(long)s1*DM + d]);
    out[idx] = fmaf(ls3[d], m, x2[idx]);
}

// ============================== host ==============================
#define SYMPF(p, s) do { void* _t; cudaGetSymbolAddress(&_t, s); p = (float*)_t; } while(0)
#define SYMPB(p, s) do { void* _t; cudaGetSymbolAddress(&_t, s); p = (bf16*)_t; } while(0)
#define SYMPI(p, s) do { void* _t; cudaGetSymbolAddress(&_t, s); p = (int*)_t; } while(0)

extern "C" void kernel_launch(void* const* d_in, const int* in_sizes, int n_in,
                              void* d_out, int out_size){
    const float* x      = (const float*)d_in[0];
    const float* rms1_w = (const float*)d_in[1];
    const float* rms2_w = (const float*)d_in[2];
    const float* rms3_w = (const float*)d_in[3];
    const float* ls1    = (const float*)d_in[4];
    const float* ls2    = (const float*)d_in[5];
    const float* ls3    = (const float*)d_in[6];
    const float* W_in   = (const float*)d_in[7];
    const float* conv_w = (const float*)d_in[8];
    const float* conv_b = (const float*)d_in[9];
    const float* W_B    = (const float*)d_in[10];
    const float* W_C    = (const float*)d_in[11];
    const float* W_dt   = (const float*)d_in[12];
    const float* b_dt   = (const float*)d_in[13];
    const float* W_out_m= (const float*)d_in[14];
    const float* Avec   = (const float*)d_in[15];
    const float* Dp     = (const float*)d_in[16];
    const float* W_qkv  = (const float*)d_in[17];
    const float* W_o    = (const float*)d_in[18];
    const float* ascale = (const float*)d_in[19];
    const float* Wg1    = (const float*)d_in[20];
    const float* bg1    = (const float*)d_in[21];
    const float* Wg2    = (const float*)d_in[22];
    const float* w1     = (const float*)d_in[23];
    const float* w2     = (const float*)d_in[24];
    const float* w3     = (const float*)d_in[25];
    float* out = (float*)d_out;

    float *p_xz, *p_xc, *p_dtBC, *p_scanp, *p_x1, *p_x2, *p_g1, *p_gs, *p_topw;
    float *p_hend, *p_h0, *p_P;
    int *p_topi, *p_cnt, *p_slot;
    bf16 *b_rms1, *b_xc, *b_ymul, *b_rms2, *b_qkv, *b_q, *b_k, *b_v, *b_att, *b_xf,
         *b_xg, *b_h, *b_eo;
    bf16 *b_Win, *b_Wout, *b_Wqkv, *b_Wo, *b_Wg1, *b_w12, *b_w3, *b_Wcat;
    float2* p_tab;

    SYMPF(p_xz, g_xz); SYMPF(p_xc, g_xc); SYMPF(p_dtBC, g_dtBC); SYMPF(p_scanp, g_scanp);
    SYMPF(p_x1, g_x1);
    SYMPF(p_x2, g_x2); SYMPF(p_g1, g_g1); SYMPF(p_gs, g_gs); SYMPF(p_topw, g_topw);
    SYMPF(p_hend, g_hend); SYMPF(p_h0, g_h0); SYMPF(p_P, g_P);
    { void* _t; cudaGetSymbolAddress(&_t, g_ropetab); p_tab = (float2*)_t; }
    SYMPI(p_topi, g_topi); SYMPI(p_cnt, g_cnt); SYMPI(p_slot, g_slot);
    SYMPB(b_rms1, g_rms1b); SYMPB(b_xc, g_xcb); SYMPB(b_ymul, g_ymulb); SYMPB(b_rms2, g_rms2b);
    SYMPB(b_qkv, g_qkvb); SYMPB(b_q, g_qb); SYMPB(b_k, g_kb); SYMPB(b_v, g_vb);
    SYMPB(b_att, g_attb); SYMPB(b_xf, g_xfb); SYMPB(b_xg, g_xgb);
    SYMPB(b_h, g_hb); SYMPB(b_eo, g_eob);
    SYMPB(b_Win, g_Winb); SYMPB(b_Wout, g_Woutb); SYMPB(b_Wqkv, g_Wqkvb); SYMPB(b_Wo, g_Wob);
    SYMPB(b_Wg1, g_Wg1b); SYMPB(b_w12, g_w12b); SYMPB(b_w3, g_w3b); SYMPB(b_Wcat, g_Wcatb);

    cudaFuncSetAttribute(bgemm256_k<0,0>, cudaFuncAttributeMaxDynamicSharedMemorySize, DSMEM256);
    cudaFuncSetAttribute(bgemm256_k<2,0>, cudaFuncAttributeMaxDynamicSharedMemorySize, DSMEM256);
    cudaFuncSetAttribute(bgemm256_k<0,1>, cudaFuncAttributeMaxDynamicSharedMemorySize, DSMEM256);
    cudaFuncSetAttribute(bgemm256_k<3,1>, cudaFuncAttributeMaxDynamicSharedMemorySize, DSMEM256);
    cudaFuncSetAttribute(flash_k, cudaFuncAttributeMaxDynamicSharedMemorySize, FSMEM);

    // ---- setup: conversions + rope table ----
    {
        long n0 = (long)DM*2*DI, n1 = (long)DI*DM, n2 = (long)DM*3*DM,
             n3 = (long)DM*DM, n4 = (long)DM*512, n5 = (long)NEXP*DFF*DM;
        long tot = n0+n1+n2+n3+n4+n5;
        convall_k<<<(int)((tot/4 + 255)/256), 256>>>(
            W_in, b_Win, n0,  W_out_m, b_Wout, n1,  W_qkv, b_Wqkv, n2,
            W_o,  b_Wo,  n3,  Wg1,     b_Wg1,  n4,  w3,    b_w3,   n5);
    }
    pack12_k<<<(int)(((long)NEXP*DM*DFF/4 + 255)/256), 256>>>(w1, w2, b_w12);
    packw_k<<<(DI*64+255)/256, 256>>>(W_dt, W_B, W_C, b_Wcat);
    ropetab_k<<<LSEQ, 64>>>(p_tab);

    // ---- 1. Mamba ----
    rmsnorm_bf_k<<<NTOK, 256>>>(x, rms1_w, b_rms1);
    {   dim3 g(2*DI/128, NTOK/256, 1);
        bgemm256_k<0,0><<<g, 256, DSMEM256>>>(b_rms1, b_Win, p_xz, NTOK, 2*DI, DM, DM, 2*DI, 2*DI,
                                              0,0,0, nullptr, nullptr, nullptr); }
    conv_k<<<(int)(((long)NTOK*DI/4+255)/256), 256>>>(p_xz, conv_w, conv_b, p_xc, b_xc);
    {   dim3 g(1, NTOK/128, 1);
        bgemm_k<<<g, 256>>>(b_xc, b_Wcat, p_dtBC, NTOK, 64, DI, DI, 64, 64); }
    scanprep_k<<<(NTOK*16+255)/256, 256>>>(p_dtBC, b_dt, Avec, p_scanp);
    {   dim3 g(16, NCH, BB);
        scanA_k<<<g, 128>>>(p_scanp, p_xc, p_hend, p_P); }
    scanComb_k<<<BB*DI/128, 128>>>(p_hend, p_P, p_h0);
    {   dim3 g(16, NCH, BB);
        scanC_k<<<g, 128>>>(p_scanp, p_xc, p_xz, Dp, p_h0, b_ymul); }
    {   dim3 g(DM/128, NTOK/256, 1);
        bgemm256_k<2,0><<<g, 256, DSMEM256>>>(b_ymul, b_Wout, p_x1, NTOK, DM, DI, DI, DM, DM,
                                              0,0,0, ls1, x, nullptr); }

    // ---- 2. Attention ----
    rmsnorm_bf_k<<<NTOK, 256>>>(p_x1, rms2_w, b_rms2);
    {   dim3 g(3*DM/128, NTOK/256, 1);
        bgemm256_k<0,1><<<g, 256, DSMEM256>>>(b_rms2, b_Wqkv, b_qkv, NTOK, 3*DM, DM, DM, 3*DM, 3*DM,
                                              0,0,0, nullptr, nullptr, nullptr); }
    rope2_k<<<NTOK, 256>>>(b_qkv, p_tab, b_q, b_k, b_v);
    {   dim3 g(LSEQ/128, BB*NH, 1);
        flash_k<<<g, 256, FSMEM>>>(b_q, b_k, b_v, ascale, b_att); }
    {   dim3 g(DM/128, NTOK/256, 1);
        bgemm256_k<2,0><<<g, 256, DSMEM256>>>(b_att, b_Wo, p_x2, NTOK, DM, DM, DM, DM, DM,
                                              0,0,0, ls2, p_x1, nullptr); }

    // ---- 3. MoE (top-2 sparse) ----
    rmsnorm_bf_k<<<NTOK, 256>>>(p_x2, rms3_w, b_xf);
    {   dim3 g(512/128, NTOK/128, 1);
        bgemm_k<<<g, 256>>>(b_xf, b_Wg1, p_g1, NTOK, 512, DM, DM, 512, 512); }
    gate2_k<<<NTOK, 64>>>(p_g1, bg1, Wg2, p_gs, p_topi, p_topw, p_cnt);
    if (out_size > NTOK*DM)
        bal_k<<<1, 256>>>(p_gs, out + (long)NTOK*DM);
    assign_k<<<(NTOK*2+255)/256, 256>>>(p_topi, p_cnt, p_slot);
    gather_k<<<NTOK*2, 128>>>(b_xf, p_slot, b_xg);
    {   dim3 g12(2*DFF/128, NTOK/256, NEXP);
        bgemm256_k<3,1><<<g12, 256, DSMEM256>>>(b_xg, b_w12, b_h,
                                      NTOK, 2*DFF, DM, DM, 2*DFF, 2*DFF,
                                      (long)NTOK*DM, (long)DM*2*DFF, (long)NTOK*DFF,
                                      nullptr, nullptr, p_cnt);
    }
    {   dim3 g3(DM/128, NTOK/256, NEXP);
        bgemm256_k<0,1><<<g3, 256, DSMEM256>>>(b_h, b_w3, b_eo,
                                     NTOK, DM, DFF, DFF, DM, DM,
                                     (long)NTOK*DFF, (long)DFF*DM, (long)NTOK*DM,
                                     nullptr, nullptr, p_cnt);
    }
    combine2_k<<<(int)(((long)NTOK*DM+255)/256), 256>>>(p_x2, ls3, b_eo, p_slot, p_topw, out);
}

// round 16
// speedup vs baseline: 1.0022x; 1.0022x over previous
#include <cuda_runtime.h>
#include <cuda_bf16.h>
#include <math.h>

#define BB   2
#define LSEQ 2048
#define DM   1024
#define DI   2048
#define NH   8
#define DH   128
#define NEXP 4
#define DFF  4096
#define NTOK (BB*LSEQ)   // 4096
#define NCH  16
#define CLEN 128         // LSEQ/NCH

typedef __nv_bfloat16 bf16;

// ---------------- static scratch ----------------
__device__ float g_xz[NTOK*2*DI];
__device__ float g_xc[NTOK*DI];
__device__ float g_dtBC[NTOK*64];
__device__ float g_scanp[NTOK*48];
__device__ float g_x1[NTOK*DM];
__device__ float g_x2[NTOK*DM];
__device__ float g_g1[NTOK*512];
__device__ float g_gs[NTOK*NEXP];
__device__ int   g_topi[NTOK*2];
__device__ float g_topw[NTOK*2];
__device__ int   g_cnt[NEXP];
__device__ int   g_slot[NTOK*2];
__device__ float g_hend[BB*NCH*DI*16];
__device__ float g_h0[BB*NCH*DI*16];
__device__ float g_P[BB*NCH*16];

// bf16 activations
__device__ bf16 g_rms1b[NTOK*DM];
__device__ bf16 g_xcb[NTOK*DI];
__device__ bf16 g_ymulb[NTOK*DI];
__device__ bf16 g_rms2b[NTOK*DM];
__device__ bf16 g_qkvb[NTOK*3*DM];
__device__ bf16 g_qb[NTOK*DM];
__device__ bf16 g_kb[NTOK*DM];
__device__ bf16 g_vb[NTOK*DM];
__device__ bf16 g_attb[NTOK*DM];
__device__ bf16 g_xfb[NTOK*DM];
__device__ bf16 g_xgb[NEXP*NTOK*DM];
__device__ bf16 g_hb[(long)NEXP*NTOK*DFF];
__device__ bf16 g_eob[NEXP*NTOK*DM];

// bf16 weights
__device__ bf16 g_Winb[DM*2*DI];
__device__ bf16 g_Woutb[DI*DM];
__device__ bf16 g_Wqkvb[DM*3*DM];
__device__ bf16 g_Wob[DM*DM];
__device__ bf16 g_Wg1b[DM*512];
__device__ bf16 g_w12b[(long)NEXP*DM*2*DFF];
__device__ bf16 g_w3b[(long)NEXP*DFF*DM];
__device__ bf16 g_Wcatb[DI*64];

__device__ __forceinline__ float siluf(float x){ return x / (1.f + expf(-x)); }

// ---------------- merged fp32 -> bf16 conversions (6 segments) ----------------
__global__ void convall_k(const float* __restrict__ s0, bf16* __restrict__ d0, long n0,
                          const float* __restrict__ s1, bf16* __restrict__ d1, long n1,
                          const float* __restrict__ s2, bf16* __restrict__ d2, long n2,
                          const float* __restrict__ s3, bf16* __restrict__ d3, long n3,
                          const float* __restrict__ s4, bf16* __restrict__ d4, long n4,
                          const float* __restrict__ s5, bf16* __restrict__ d5, long n5){
    long i = ((long)blockIdx.x*blockDim.x + threadIdx.x)*4;
    const float* s; bf16* d;
    if (i < n0){ s = s0; d = d0; }
    else { i -= n0;
    if (i < n1){ s = s1; d = d1; }
    else { i -= n1;
    if (i < n2){ s = s2; d = d2; }
    else { i -= n2;
    if (i < n3){ s = s3; d = d3; }
    else { i -= n3;
    if (i < n4){ s = s4; d = d4; }
    else { i -= n4;
    if (i >= n5) return;
    s = s5; d = d5; }}}}}
    float4 v = *reinterpret_cast<const float4*>(s + i);
    *reinterpret_cast<__nv_bfloat162*>(d + i)     = __floats2bfloat162_rn(v.x, v.y);
    *reinterpret_cast<__nv_bfloat162*>(d + i + 2) = __floats2bfloat162_rn(v.z, v.w);
}

// pack w1|w2 INTERLEAVED
__global__ void pack12_k(const float* __restrict__ w1, const float* __restrict__ w2,
                         bf16* __restrict__ o){
    long i = ((long)blockIdx.x*blockDim.x + threadIdx.x)*4;
    if (i >= (long)NEXP*DM*DFF) return;
    long row = i >> 12;
    int  j   = (int)(i & 4095);
    float4 a = *reinterpret_cast<const float4*>(w1 + i);
    float4 b = *reinterpret_cast<const float4*>(w2 + i);
    bf16* d1 = o + row*(2*DFF) + 2*j;
    *reinterpret_cast<__nv_bfloat162*>(d1)   = __floats2bfloat162_rn(a.x, b.x);
    *reinterpret_cast<__nv_bfloat162*>(d1+2) = __floats2bfloat162_rn(a.y, b.y);
    *reinterpret_cast<__nv_bfloat162*>(d1+4) = __floats2bfloat162_rn(a.z, b.z);
    *reinterpret_cast<__nv_bfloat162*>(d1+6) = __floats2bfloat162_rn(a.w, b.w);
}

// pack [W_dt | W_B | W_C | 0] -> [2048][64] bf16
__global__ void packw_k(const float* __restrict__ Wdt, const float* __restrict__ WB,
                        const float* __restrict__ WC, bf16* __restrict__ o){
    int idx = blockIdx.x*256 + threadIdx.x;
    if (idx >= DI*64) return;
    int j = idx >> 6, n = idx & 63;
    float v = 0.f;
    if (n < 16) v = Wdt[j*16+n];
    else if (n < 32) v = WB[j*16+n-16];
    else if (n < 48) v = WC[j*16+n-32];
    o[idx] = __float2bfloat16(v);
}

// ---------------- RMSNorm -> bf16 (vectorized, warp reduce) ----------------
__global__ void rmsnorm_bf_k(const float* __restrict__ x, const float* __restrict__ w,
                             bf16* __restrict__ o){
    int row = blockIdx.x;
    int tid = threadIdx.x;
    const float* xr = x + (long)row*DM;
    float4 v = *reinterpret_cast<const float4*>(xr + tid*4);
    float s = v.x*v.x + v.y*v.y + v.z*v.z + v.w*v.w;
    #pragma unroll
    for (int off = 16; off > 0; off >>= 1)
        s += __shfl_xor_sync(0xffffffffu, s, off);
    __shared__ float red[8];
    if ((tid & 31) == 0) red[tid >> 5] = s;
    __syncthreads();
    float tot = red[0] + red[1] + red[2] + red[3]
              + red[4] + red[5] + red[6] + red[7];
    float r = rsqrtf(tot/(float)DM + 1e-6f);
    float4 wv = *reinterpret_cast<const float4*>(w + tid*4);
    bf16* ob = o + (long)row*DM + tid*4;
    *reinterpret_cast<__nv_bfloat162*>(ob)   = __floats2bfloat162_rn(wv.x*v.x*r, wv.y*v.y*r);
    *reinterpret_cast<__nv_bfloat162*>(ob+2) = __floats2bfloat162_rn(wv.z*v.z*r, wv.w*v.w*r);
}

// ---------------- MMA primitives ----------------
__device__ __forceinline__ void cpasync16(unsigned dst, const void* src, int ssz){
    asm volatile("cp.async.ca.shared.global [%0], [%1], 16, %2;"
        :: "r"(dst), "l"(src), "r"(ssz));
}
__device__ __forceinline__ void cp_commit(){ asm volatile("cp.async.commit_group;"); }
__device__ __forceinline__ void cp_wait0(){ asm volatile("cp.async.wait_group 0;"); }
__device__ __forceinline__ void cp_wait1(){ asm volatile("cp.async.wait_group 1;"); }
__device__ __forceinline__ void ldsm_x4(unsigned saddr, unsigned &o0, unsigned &o1,
                                        unsigned &o2, unsigned &o3){
    asm volatile("ldmatrix.sync.aligned.m8n8.x4.shared.b16 {%0,%1,%2,%3},[%4];"
        : "=r"(o0),"=r"(o1),"=r"(o2),"=r"(o3) : "r"(saddr));
}
__device__ __forceinline__ void ldsm_x4_t(unsigned saddr, unsigned &o0, unsigned &o1,
                                          unsigned &o2, unsigned &o3){
    asm volatile("ldmatrix.sync.aligned.m8n8.x4.trans.shared.b16 {%0,%1,%2,%3},[%4];"
        : "=r"(o0),"=r"(o1),"=r"(o2),"=r"(o3) : "r"(saddr));
}
__device__ __forceinline__ void mma16816(float* d, const unsigned* am, const unsigned* bm){
    asm volatile("mma.sync.aligned.m16n8k16.row.col.f32.bf16.bf16.f32 "
        "{%0,%1,%2,%3},{%4,%5,%6,%7},{%8,%9},{%0,%1,%2,%3};"
        : "+f"(d[0]),"+f"(d[1]),"+f"(d[2]),"+f"(d[3])
        : "r"(am[0]),"r"(am[1]),"r"(am[2]),"r"(am[3]), "r"(bm[0]),"r"(bm[1]));
}
__device__ __forceinline__ unsigned pkbf2(float x, float y){
    __nv_bfloat162 t = __floats2bfloat162_rn(x, y);
    return *reinterpret_cast<unsigned*>(&t);
}

// ---------------- 128x128 GEMM (fp32 out, no epilogue) ----------------
__device__ __forceinline__ void stage_tiles(const bf16* Ab, const bf16* Bb,
    int bm, int bn, int N, int lda, int ldb, int k0, int tid,
    unsigned Adst, unsigned Bdst)
{
    #pragma unroll
    for (int c = tid; c < 512; c += 256){
        int r  = c >> 2;
        int ko = (c & 3) << 3;
        cpasync16(Adst + 2u*(unsigned)(r*40 + ko),
                  Ab + (long)(bm + r)*lda + k0 + ko, 16);
    }
    #pragma unroll
    for (int c = tid; c < 512; c += 256){
        int r  = c >> 4;
        int no = (c & 15) << 3;
        const bf16* src = Bb + (long)(k0 + r)*ldb + bn + no;
        int ssz = 16;
        if (bn + no >= N){ src = Bb; ssz = 0; }
        cpasync16(Bdst + 2u*(unsigned)(r*136 + no), src, ssz);
    }
}

__global__ void __launch_bounds__(256) bgemm_k(
    const bf16* __restrict__ Aptr, const bf16* __restrict__ Bptr, float* __restrict__ Cv,
    int M, int N, int K, int lda, int ldb, int ldc)
{
    __shared__ bf16 As[3*5120];
    __shared__ bf16 Bs[3*5120];
    const int bm = blockIdx.y * 128;
    const int bn = blockIdx.x * 128;
    const int tid  = threadIdx.x;
    const int lane = tid & 31;
    const int warp = tid >> 5;
    const int wm = warp >> 1;
    const int wn = warp & 1;

    float acc[2][8][4];
    #pragma unroll
    for (int i = 0; i < 2; i++)
        #pragma unroll
        for (int j = 0; j < 8; j++)
            #pragma unroll
            for (int q = 0; q < 4; q++) acc[i][j][q] = 0.f;

    unsigned Afrag[2][4];
    unsigned Bfrag[8][2];

    const unsigned As_base = (unsigned)__cvta_generic_to_shared(As);
    const unsigned Bs_base = (unsigned)__cvta_generic_to_shared(Bs);

    const int rowA = wm*32 + (lane & 15);
    const int colA = (lane >> 4) * 8;
    unsigned aoff0 = As_base + 2u*(unsigned)( rowA       *40 + colA);
    unsigned aoff1 = As_base + 2u*(unsigned)((rowA + 16) *40 + colA);

    unsigned boff[4];
    #pragma unroll
    for (int p = 0; p < 4; p++){
        int brow = lane & 15;
        int bcol = (lane >> 4) * 8;
        boff[p] = Bs_base + 2u*(unsigned)(brow*136 + wn*64 + p*16 + bcol);
    }

    const int nk = K >> 5;
    stage_tiles(Aptr, Bptr, bm, bn, N, lda, ldb, 0, tid, As_base, Bs_base);
    cp_commit();
    if (nk > 1){
        stage_tiles(Aptr, Bptr, bm, bn, N, lda, ldb, 32, tid,
                    As_base + 10240u, Bs_base + 10240u);
        cp_commit();
    }

    unsigned sb = 0u;
    for (int it = 0; it < nk; it++){
        if (it + 1 < nk) cp_wait1(); else cp_wait0();
        __syncthreads();
        if (it + 2 < nk){
            unsigned off = (unsigned)((it + 2) % 3) * 10240u;
            stage_tiles(Aptr, Bptr, bm, bn, N, lda, ldb, (it+2) << 5, tid,
                        As_base + off, Bs_base + off);
            cp_commit();
        }
        #pragma unroll
        for (int ks = 0; ks < 32; ks += 16){
            ldsm_x4(aoff0 + sb + 2u*ks, Afrag[0][0], Afrag[0][1], Afrag[0][2], Afrag[0][3]);
            ldsm_x4(aoff1 + sb + 2u*ks, Afrag[1][0], Afrag[1][1], Afrag[1][2], Afrag[1][3]);
            #pragma unroll
            for (int p = 0; p < 4; p++){
                unsigned ba = boff[p] + sb + 2u*(unsigned)(ks*136);
                ldsm_x4_t(ba, Bfrag[2*p][0], Bfrag[2*p][1],
                              Bfrag[2*p+1][0], Bfrag[2*p+1][1]);
            }
            #pragma unroll
            for (int mt = 0; mt < 2; mt++)
                #pragma unroll
                for (int nt = 0; nt < 8; nt++)
                    mma16816(acc[mt][nt], Afrag[mt], Bfrag[nt]);
        }
        sb += 10240u;
        if (sb == 30720u) sb = 0u;
    }

    #pragma unroll
    for (int mt = 0; mt < 2; mt++){
        int r0 = bm + wm*32 + mt*16 + (lane >> 2);
        #pragma unroll
        for (int nt = 0; nt < 8; nt++){
            int col = bn + wn*64 + nt*8 + ((lane & 3) << 1);
            if (col < N){
                *reinterpret_cast<float2*>(&Cv[(long)r0*ldc + col]) =
                    make_float2(acc[mt][nt][0], acc[mt][nt][1]);
                *reinterpret_cast<float2*>(&Cv[(long)(r0+8)*ldc + col]) =
                    make_float2(acc[mt][nt][2], acc[mt][nt][3]);
            }
        }
    }
}

// ---------------- 256x128 GEMM, 3 slots x 64-K groups, dynamic smem ----------------
#define GSLOT_A 40960u
#define GSLOT_B 17408u
#define DSMEM256 (3*(GSLOT_A + GSLOT_B))

__device__ __forceinline__ void stage256(const bf16* Ab, const bf16* Bb,
    int bm, int bn, int N, int lda, int ldb, int k0, int tid,
    unsigned Adst, unsigned Bdst)
{
    #pragma unroll
    for (int c = tid; c < 1024; c += 256){
        int r  = c >> 2;
        int ko = (c & 3) << 3;
        cpasync16(Adst + 2u*(unsigned)(r*40 + ko),
                  Ab + (long)(bm + r)*lda + k0 + ko, 16);
    }
    #pragma unroll
    for (int c = tid; c < 512; c += 256){
        int r  = c >> 4;
        int no = (c & 15) << 3;
        const bf16* src = Bb + (long)(k0 + r)*ldb + bn + no;
        int ssz = 16;
        if (bn + no >= N){ src = Bb; ssz = 0; }
        cpasync16(Bdst + 2u*(unsigned)(r*136 + no), src, ssz);
    }
}

// EPI: 0 none, 1 relu(acc+bias) fp32, 2 resid fp32, 3 siluGLU bf16
template<int EPI, int OUTBF>
__global__ void __launch_bounds__(256) bgemm256_k(
    const bf16* __restrict__ Aptr, const bf16* __restrict__ Bptr, void* __restrict__ Cv,
    int M, int N, int K, int lda, int ldb, int ldc,
    long sA, long sB, long sC, const float* __restrict__ bias,
    const float* __restrict__ resx, const int* __restrict__ mcnt)
{
    extern __shared__ bf16 dsm[];
    const int bm = blockIdx.y * 256;
    int Meff = M;
    if (mcnt) Meff = mcnt[blockIdx.z];
    if (bm >= Meff) return;
    const bf16* Ab = Aptr + (long)blockIdx.z * sA;
    const bf16* Bb = Bptr + (long)blockIdx.z * sB;
    const int bn = blockIdx.x * 128;
    const int tid  = threadIdx.x;
    const int lane = tid & 31;
    const int warp = tid >> 5;
    const int wm = warp >> 1;
    const int wn = warp & 1;

    float acc[4][8][4];
    #pragma unroll
    for (int i = 0; i < 4; i++)
        #pragma unroll
        for (int j = 0; j < 8; j++)
            #pragma unroll
            for (int q = 0; q < 4; q++) acc[i][j][q] = 0.f;

    unsigned Afrag[4][4];
    unsigned Bfrag[8][2];

    const unsigned As_base = (unsigned)__cvta_generic_to_shared(dsm);
    const unsigned Bs_base = As_base + 3u*GSLOT_A;

    const int rowA = wm*64 + (lane & 15);
    const int colA = (lane >> 4) * 8;
    unsigned aoff[4];
    #pragma unroll
    for (int mt = 0; mt < 4; mt++)
        aoff[mt] = As_base + 2u*(unsigned)((rowA + mt*16)*40 + colA);

    unsigned boff[4];
    {
        int brow = lane & 15;
        int bcol = (lane >> 4) * 8;
        #pragma unroll
        for (int p = 0; p < 4; p++)
            boff[p] = Bs_base + 2u*(unsigned)(brow*136 + wn*64 + p*16 + bcol);
    }

    const int ng = K >> 6;
    stage256(Ab, Bb, bm, bn, N, lda, ldb, 0,  tid, As_base,           Bs_base);
    stage256(Ab, Bb, bm, bn, N, lda, ldb, 32, tid, As_base + 20480u,  Bs_base + 8704u);
    cp_commit();
    if (ng > 1){
        stage256(Ab, Bb, bm, bn, N, lda, ldb, 64, tid, As_base + GSLOT_A,           Bs_base + GSLOT_B);
        stage256(Ab, Bb, bm, bn, N, lda, ldb, 96, tid, As_base + GSLOT_A + 20480u,  Bs_base + GSLOT_B + 8704u);
        cp_commit();
    }

    for (int g = 0; g < ng; g++){
        if (g + 1 < ng) cp_wait1(); else cp_wait0();
        __syncthreads();
        if (g + 2 < ng){
            unsigned sl = (unsigned)((g + 2) % 3);
            int k0 = (g + 2) << 6;
            stage256(Ab, Bb, bm, bn, N, lda, ldb, k0,      tid,
                     As_base + sl*GSLOT_A,           Bs_base + sl*GSLOT_B);
            stage256(Ab, Bb, bm, bn, N, lda, ldb, k0 + 32, tid,
                     As_base + sl*GSLOT_A + 20480u,  Bs_base + sl*GSLOT_B + 8704u);
            cp_commit();
        }
        unsigned slA = (unsigned)(g % 3) * GSLOT_A;
        unsigned slB = (unsigned)(g % 3) * GSLOT_B;
        #pragma unroll
        for (int sub = 0; sub < 2; sub++){
            unsigned sa  = slA + (unsigned)sub*20480u;
            unsigned sbb = slB + (unsigned)sub*8704u;
            #pragma unroll
            for (int ks = 0; ks < 32; ks += 16){
                #pragma unroll
                for (int mt = 0; mt < 4; mt++)
                    ldsm_x4(aoff[mt] + sa + 2u*ks,
                            Afrag[mt][0], Afrag[mt][1], Afrag[mt][2], Afrag[mt][3]);
                #pragma unroll
                for (int p = 0; p < 4; p++){
                    unsigned ba = boff[p] + sbb + 2u*(unsigned)(ks*136);
                    ldsm_x4_t(ba, Bfrag[2*p][0], Bfrag[2*p][1],
                                  Bfrag[2*p+1][0], Bfrag[2*p+1][1]);
                }
                #pragma unroll
                for (int mt = 0; mt < 4; mt++)
                    #pragma unroll
                    for (int nt = 0; nt < 8; nt++)
                        mma16816(acc[mt][nt], Afrag[mt], Bfrag[nt]);
            }
        }
    }

    #pragma unroll
    for (int mt = 0; mt < 4; mt++){
        int r0 = bm + wm*64 + mt*16 + (lane >> 2);
        #pragma unroll
        for (int nt = 0; nt < 8; nt++){
            int col = bn + wn*64 + nt*8 + ((lane & 3) << 1);
            if (col < N){
                float v0 = acc[mt][nt][0];
                float v1 = acc[mt][nt][1];
                float v2 = acc[mt][nt][2];
                float v3 = acc[mt][nt][3];
                if (EPI == 3){
                    bf16* Cb = (bf16*)Cv + (long)blockIdx.z * sC;
                    int jc = col >> 1;
                    Cb[(long)r0*(N>>1) + jc]     = __float2bfloat16(siluf(v0)*v1);
                    Cb[(long)(r0+8)*(N>>1) + jc] = __float2bfloat16(siluf(v2)*v3);
                    continue;
                }
                if (EPI == 1){
                    float b0 = bias[col];
                    float b1 = bias[col+1];
                    v0 = fmaxf(v0+b0, 0.f); v1 = fmaxf(v1+b1, 0.f);
                    v2 = fmaxf(v2+b0, 0.f); v3 = fmaxf(v3+b1, 0.f);
                }
                if (EPI == 2){
                    float b0 = bias[col];
                    float b1 = bias[col+1];
                    v0 = fmaf(b0, v0, resx[(long)r0*ldc + col]);
                    v1 = fmaf(b1, v1, resx[(long)r0*ldc + col + 1]);
                    v2 = fmaf(b0, v2, resx[(long)(r0+8)*ldc + col]);
                    v3 = fmaf(b1, v3, resx[(long)(r0+8)*ldc + col + 1]);
                }
                if (OUTBF){
                    bf16* Cb = (bf16*)Cv + (long)blockIdx.z * sC;
                    *reinterpret_cast<__nv_bfloat162*>(&Cb[(long)r0*ldc + col]) =
                        __floats2bfloat162_rn(v0, v1);
                    *reinterpret_cast<__nv_bfloat162*>(&Cb[(long)(r0+8)*ldc + col]) =
                        __floats2bfloat162_rn(v2, v3);
                } else {
                    float* Cb = (float*)Cv + (long)blockIdx.z * sC;
                    *reinterpret_cast<float2*>(&Cb[(long)r0*ldc + col]) = make_float2(v0, v1);
                    *reinterpret_cast<float2*>(&Cb[(long)(r0+8)*ldc + col]) = make_float2(v2, v3);
                }
            }
        }
    }
}

// ---------------- fused flash attention ----------------
#define FTILE (128*136)
#define FSMEM (5*FTILE*2)

__device__ __forceinline__ void fstage(const bf16* src, unsigned dst, int tid){
    for (int i = tid; i < 2048; i += 256){
        int r = i >> 4, c = (i & 15) << 3;
        cpasync16(dst + 2u*(unsigned)(r*136 + c), src + r*DH + c, 16);
    }
}

__global__ void __launch_bounds__(256, 1) flash_k(
    const bf16* __restrict__ q, const bf16* __restrict__ k, const bf16* __restrict__ v,
    const float* __restrict__ ascale, bf16* __restrict__ att)
{
    extern __shared__ bf16 fs[];
    const int qt = blockIdx.x, bh = blockIdx.y;
    const int bb = bh >> 3, hh = bh & 7;
    const int tid = threadIdx.x, lane = tid & 31, w = tid >> 5;
    const float a = ascale[hh];

    const bf16* qg = q + ((long)bh*LSEQ + qt*128)*DH;
    const bf16* kg = k + (long)bh*LSEQ*DH;
    const bf16* vg = v + (long)bh*LSEQ*DH;

    const unsigned Qb = (unsigned)__cvta_generic_to_shared(fs);
    const unsigned Kb = Qb + 2u*FTILE;
    const unsigned Vb = Qb + 6u*FTILE;
    const unsigned TILEB = 2u*FTILE;

    fstage(qg, Qb, tid);
    fstage(kg, Kb, tid);
    fstage(vg, Vb, tid);
    cp_commit();
    cp_wait0();
    __syncthreads();

    unsigned qf[8][4];
    {
        int rq = w*16 + (lane & 15);
        int cq = (lane >> 4) << 3;
        #pragma unroll
        for (int ks = 0; ks < 8; ks++)
            ldsm_x4(Qb + 2u*(unsigned)(rq*136 + ks*16 + cq),
                    qf[ks][0], qf[ks][1], qf[ks][2], qf[ks][3]);
    }

    const int brow = (lane & 7) + (((lane >> 4) & 1) << 3);
    const int bcol = ((lane >> 3) & 1) << 3;
    unsigned kadr[8], vadr[8];
    #pragma unroll
    for (int p = 0; p < 8; p++){
        kadr[p] = Kb + 2u*(unsigned)((p*16 + brow)*136 + bcol);
        vadr[p] = Vb + 2u*(unsigned)((lane & 15)*136 + p*16 + ((lane >> 4) << 3));
    }

    float oacc[16][4];
    #pragma unroll
    for (int nt = 0; nt < 16; nt++)
        #pragma unroll
        for (int qq = 0; qq < 4; qq++) oacc[nt][qq] = 0.f;
    float m0 = -1e30f, m1 = -1e30f, l0 = 0.f, l1 = 0.f;

    for (int kt = 0; kt < 16; kt++){
        if (kt > 0){ cp_wait0(); __syncthreads(); }
        if (kt + 1 < 16){
            unsigned off = ((kt + 1) & 1) ? TILEB : 0u;
            fstage(kg + (long)(kt+1)*128*DH, Kb + off, tid);
            fstage(vg + (long)(kt+1)*128*DH, Vb + off, tid);
            cp_commit();
        }
        const unsigned sb = (kt & 1) ? TILEB : 0u;

        float sacc[16][4];
        #pragma unroll
        for (int nt = 0; nt < 16; nt++)
            #pragma unroll
            for (int qq = 0; qq < 4; qq++) sacc[nt][qq] = 0.f;

        #pragma unroll
        for (int ks = 0; ks < 8; ks++){
            #pragma unroll
            for (int p = 0; p < 8; p++){
                unsigned bf0[2], bf1[2];
                ldsm_x4(kadr[p] + sb + 2u*(unsigned)(ks*16),
                        bf0[0], bf0[1], bf1[0], bf1[1]);
                mma16816(sacc[2*p],   qf[ks], bf0);
                mma16816(sacc[2*p+1], qf[ks], bf1);
            }
        }

        float ax0 = -1e30f, ax1 = -1e30f;
        #pragma unroll
        for (int nt = 0; nt < 16; nt++){
            sacc[nt][0] *= a; sacc[nt][1] *= a; sacc[nt][2] *= a; sacc[nt][3] *= a;
            ax0 = fmaxf(ax0, fmaxf(sacc[nt][0], sacc[nt][1]));
            ax1 = fmaxf(ax1, fmaxf(sacc[nt][2], sacc[nt][3]));
        }
        ax0 = fmaxf(ax0, __shfl_xor_sync(0xffffffffu, ax0, 1));
        ax0 = fmaxf(ax0, __shfl_xor_sync(0xffffffffu, ax0, 2));
        ax1 = fmaxf(ax1, __shfl_xor_sync(0xffffffffu, ax1, 1));
        ax1 = fmaxf(ax1, __shfl_xor_sync(0xffffffffu, ax1, 2));
        float mn0 = fmaxf(m0, ax0), mn1 = fmaxf(m1, ax1);
        float f0 = expf(m0 - mn0), f1 = expf(m1 - mn1);

        float rs0 = 0.f, rs1 = 0.f;
        #pragma unroll
        for (int nt = 0; nt < 16; nt++){
            sacc[nt][0] = expf(sacc[nt][0] - mn0);
            sacc[nt][1] = expf(sacc[nt][1] - mn0);
            sacc[nt][2] = expf(sacc[nt][2] - mn1);
            sacc[nt][3] = expf(sacc[nt][3] - mn1);
            rs0 += sacc[nt][0] + sacc[nt][1];
            rs1 += sacc[nt][2] + sacc[nt][3];
        }
        rs0 += __shfl_xor_sync(0xffffffffu, rs0, 1);
        rs0 += __shfl_xor_sync(0xffffffffu, rs0, 2);
        rs1 += __shfl_xor_sync(0xffffffffu, rs1, 1);
        rs1 += __shfl_xor_sync(0xffffffffu, rs1, 2);
        l0 = l0*f0 + rs0; l1 = l1*f1 + rs1;
        m0 = mn0; m1 = mn1;

        #pragma unroll
        for (int nt = 0; nt < 16; nt++){
            oacc[nt][0] *= f0; oacc[nt][1] *= f0;
            oacc[nt][2] *= f1; oacc[nt][3] *= f1;
        }

        unsigned pa[8][4];
        #pragma unroll
        for (int ksp = 0; ksp < 8; ksp++){
            pa[ksp][0] = pkbf2(sacc[2*ksp][0],   sacc[2*ksp][1]);
            pa[ksp][1] = pkbf2(sacc[2*ksp][2],   sacc[2*ksp][3]);
            pa[ksp][2] = pkbf2(sacc[2*ksp+1][0], sacc[2*ksp+1][1]);
            pa[ksp][3] = pkbf2(sacc[2*ksp+1][2], sacc[2*ksp+1][3]);
        }

        #pragma unroll
        for (int ksp = 0; ksp < 8; ksp++){
            #pragma unroll
            for (int p = 0; p < 8; p++){
                unsigned bf0[2], bf1[2];
                ldsm_x4_t(vadr[p] + sb + 2u*(unsigned)(ksp*16*136),
                          bf0[0], bf0[1], bf1[0], bf1[1]);
                mma16816(oacc[2*p],   pa[ksp], bf0);
                mma16816(oacc[2*p+1], pa[ksp], bf1);
            }
        }
    }

    float inv0 = 1.f / l0, inv1 = 1.f / l1;
    long row0 = (long)bb*LSEQ + qt*128 + w*16 + (lane >> 2);
    long row1 = row0 + 8;
    int  cbase = hh*DH + ((lane & 3) << 1);
    #pragma unroll
    for (int nt = 0; nt < 16; nt++){
        int col = cbase + nt*8;
        *reinterpret_cast<__nv_bfloat162*>(&att[row0*DM + col]) =
            __floats2bfloat162_rn(oacc[nt][0]*inv0, oacc[nt][1]*inv0);
        *reinterpret_cast<__nv_bfloat162*>(&att[row1*DM + col]) =
            __floats2bfloat162_rn(oacc[nt][2]*inv1, oacc[nt][3]*inv1);
    }
}

// ---------------- depthwise conv + bias + SiLU (4-wide vectorized) ----------------
__global__ void conv_k(const float* __restrict__ xz, const float* __restrict__ cw,
                       const float* __restrict__ cb, float* __restrict__ xc,
                       bf16* __restrict__ xcb){
    long idx4 = (long)blockIdx.x*blockDim.x + threadIdx.x;
    if (idx4 >= (long)NTOK*DI/4) return;
    long idx = idx4 * 4;
    int d = (int)(idx % DI);
    int row = (int)(idx / DI);
    int t = row % LSEQ, b = row / LSEQ;
    float4 s = *reinterpret_cast<const float4*>(cb + d);
    float4 w0 = *reinterpret_cast<const float4*>(cw + d*4);
    float4 w1 = *reinterpret_cast<const float4*>(cw + (d+1)*4);
    float4 w2 = *reinterpret_cast<const float4*>(cw + (d+2)*4);
    float4 w3 = *reinterpret_cast<const float4*>(cw + (d+3)*4);
    const float* base = xz + (long)(b*LSEQ)*(2*DI) + d;
    #pragma unroll
    for (int k = 0; k < 4; k++){
        int tt = t + k - 2;
        if (tt >= 0 && tt < LSEQ){
            float4 xv = *reinterpret_cast<const float4*>(base + (long)tt*(2*DI));
            float wk0 = (k==0)?w0.x:(k==1)?w0.y:(k==2)?w0.z:w0.w;
            float wk1 = (k==0)?w1.x:(k==1)?w1.y:(k==2)?w1.z:w1.w;
            float wk2 = (k==0)?w2.x:(k==1)?w2.y:(k==2)?w2.z:w2.w;
            float wk3 = (k==0)?w3.x:(k==1)?w3.y:(k==2)?w3.z:w3.w;
            s.x = fmaf(wk0, xv.x, s.x);
            s.y = fmaf(wk1, xv.y, s.y);
            s.z = fmaf(wk2, xv.z, s.z);
            s.w = fmaf(wk3, xv.w, s.w);
        }
    }
    float4 v = make_float4(siluf(s.x), siluf(s.y), siluf(s.z), siluf(s.w));
    *reinterpret_cast<float4*>(xc + idx) = v;
    *reinterpret_cast<__nv_bfloat162*>(xcb + idx)     = __floats2bfloat162_rn(v.x, v.y);
    *reinterpret_cast<__nv_bfloat162*>(xcb + idx + 2) = __floats2bfloat162_rn(v.z, v.w);
}

// ---------------- scan preprocessing ----------------
__global__ void scanprep_k(const float* __restrict__ dtBC, const float* __restrict__ bdt,
                           const float* __restrict__ A, float* __restrict__ sp){
    int idx = blockIdx.x*blockDim.x + threadIdx.x;
    if (idx >= NTOK*16) return;
    int n = idx & 15, row = idx >> 4;
    float dtp = dtBC[(long)row*64 + n] + bdt[n];
    float dt  = fmaxf(dtp, 0.f) + log1pf(expf(-fabsf(dtp)));
    sp[(long)row*48 + n]      = expf(dt * A[n]);
    sp[(long)row*48 + 16 + n] = dt * dtBC[(long)row*64 + 16 + n];
    sp[(long)row*48 + 32 + n] = dtBC[(long)row*64 + 32 + n];
}

// ---------------- chunked selective scan (P folded into A) ----------------
__global__ void scanA_k(const float* __restrict__ sp, const float* __restrict__ xc,
                        float* __restrict__ hend, float* __restrict__ P){
    int b = blockIdx.z, ch = blockIdx.y;
    int d = blockIdx.x*128 + threadIdx.x;
    __shared__ float s[CLEN*48];
    const float* src = sp + ((long)b*LSEQ + ch*CLEN)*48;
    for (int i = threadIdx.x; i < CLEN*48; i += 128) s[i] = src[i];
    __syncthreads();
    if (blockIdx.x == 0 && threadIdx.x < 16){
        int n = threadIdx.x;
        float p = 1.f;
        for (int t = 0; t < CLEN; t++) p *= s[t*48 + n];
        P[(b*NCH + ch)*16 + n] = p;
    }
    float h[16];
    #pragma unroll
    for (int n = 0; n < 16; n++) h[n] = 0.f;
    long rowbase = (long)b*LSEQ + ch*CLEN;
    float xv_next = xc[rowbase*DI + d];
    for (int tt = 0; tt < CLEN; tt++){
        float xv = xv_next;
        if (tt + 1 < CLEN) xv_next = xc[(rowbase + tt + 1)*DI + d];
        const float* e = s + tt*48;
        #pragma unroll
        for (int n = 0; n < 16; n++)
            h[n] = fmaf(e[n], h[n], e[16+n]*xv);
    }
    float* o = hend + (((long)(b*NCH + ch)*DI + d) << 4);
    #pragma unroll
    for (int n = 0; n < 16; n += 4)
        *reinterpret_cast<float4*>(o + n) = make_float4(h[n], h[n+1], h[n+2], h[n+3]);
}

__global__ void scanComb_k(const float* __restrict__ hend, const float* __restrict__ P,
                           float* __restrict__ h0){
    int g = blockIdx.x*128 + threadIdx.x;
    int b = g / DI, d = g % DI;
    __shared__ float sP[NCH*16];
    for (int i = threadIdx.x; i < NCH*16; i += 128) sP[i] = P[b*NCH*16 + i];
    __syncthreads();
    float h[16];
    #pragma unroll
    for (int n = 0; n < 16; n++) h[n] = 0.f;
    {
        float* o = h0 + (((long)(b*NCH)*DI + d) << 4);
        #pragma unroll
        for (int n = 0; n < 16; n += 4)
            *reinterpret_cast<float4*>(o + n) = make_float4(0.f, 0.f, 0.f, 0.f);
    }
    for (int c = 1; c < NCH; c++){
        const float* he = hend + (((long)(b*NCH + c - 1)*DI + d) << 4);
        #pragma unroll
        for (int n = 0; n < 16; n++)
            h[n] = fmaf(sP[(c-1)*16 + n], h[n], he[n]);
        float* o = h0 + (((long)(b*NCH + c)*DI + d) << 4);
        #pragma unroll
        for (int n = 0; n < 16; n += 4)
            *reinterpret_cast<float4*>(o + n) = make_float4(h[n], h[n+1], h[n+2], h[n+3]);
    }
}

__global__ void scanC_k(const float* __restrict__ sp, const float* __restrict__ xc,
                        const float* __restrict__ xz, const float* __restrict__ Dp,
                        const float* __restrict__ h0, bf16* __restrict__ ymulb){
    int b = blockIdx.z, ch = blockIdx.y;
    int d = blockIdx.x*128 + threadIdx.x;
    __shared__ float s[CLEN*48];
    const float* src = sp + ((long)b*LSEQ + ch*CLEN)*48;
    for (int i = threadIdx.x; i < CLEN*48; i += 128) s[i] = src[i];
    __syncthreads();
    float h[16];
    {   const float* hi = h0 + (((long)(b*NCH + ch)*DI + d) << 4);
        #pragma unroll
        for (int n = 0; n < 16; n += 4){
            float4 v = *reinterpret_cast<const float4*>(hi + n);
            h[n] = v.x; h[n+1] = v.y; h[n+2] = v.z; h[n+3] = v.w;
        }
    }
    const float dpv = Dp[d];
    long rowbase = (long)b*LSEQ + ch*CLEN;
    float xv_next = xc[rowbase*DI + d];
    float z_next  = xz[rowbase*(2*DI) + DI + d];
    for (int tt = 0; tt < CLEN; tt++){
        float xv = xv_next;
        float z  = z_next;
        if (tt + 1 < CLEN){
            xv_next = xc[(rowbase + tt + 1)*DI + d];
            z_next  = xz[(rowbase + tt + 1)*(2*DI) + DI + d];
        }
        const float* e = s + tt*48;
        float y = 0.f;
        #pragma unroll
        for (int n = 0; n < 16; n++){
            h[n] = fmaf(e[n], h[n], e[16+n]*xv);
            y = fmaf(h[n], e[32+n], y);
        }
        ymulb[(rowbase + tt)*DI + d] = __float2bfloat16((y + dpv*xv) * siluf(z));
    }
}

// ---------------- RoPE (bf16 qkv in) -> qb,kb,vb bf16 ----------------
__global__ void rope2_k(const bf16* __restrict__ qkv, bf16* __restrict__ qb,
                        bf16* __restrict__ kb, bf16* __restrict__ vb){
    int row = blockIdx.x;
    int t = row % LSEQ, b = row / LSEQ;
    __shared__ float q[DM], kk[DM];
    const bf16* base = qkv + (long)row*3*DM;
    for (int i = threadIdx.x; i < DM; i += 256){
        q[i]  = __bfloat162float(base[i]);
        kk[i] = __bfloat162float(base[DM+i]);
    }
    __syncthreads();
    const float sq = sqrtf((float)DH);
    const float lg = logf(10000.f) / 64.f;
    for (int idx = threadIdx.x; idx < DM; idx += 256){
        int h = idx / DH, i = idx % DH;
        int j = i & 63;
        float inv = expf(-(float)j * lg);
        float ang = (float)t * inv;
        float c = cosf(ang), s = sinf(ang);
        int off = h * DH;
        float rq, rk;
        if (i < 64){ rq = -q[off + 2*i + 1]; rk = -kk[off + 2*i + 1]; }
        else       { rq =  q[off + 2*(i-64)]; rk =  kk[off + 2*(i-64)]; }
        long o = ((long)(b*NH + h)*LSEQ + t)*DH + i;
        qb[o] = __float2bfloat16((q[idx]*c + rq*s) * sq);
        kb[o] = __float2bfloat16(kk[idx]*c + rk*s);
        vb[o] = base[2*DM + idx];
    }
}

// ---------------- gate stage 2 (bias+relu folded in; zeroes counters) ----------------
__global__ void gate2_k(const float* __restrict__ g1, const float* __restrict__ bg1,
                        const float* __restrict__ Wg2,
                        float* __restrict__ gs, int* __restrict__ topi, float* __restrict__ topw,
                        int* __restrict__ cnt){
    int row = blockIdx.x;
    int tid = threadIdx.x;
    if (row == 0 && tid < NEXP) cnt[tid] = 0;
    __shared__ float red[64*4];
    float a[4] = {0.f,0.f,0.f,0.f};
    for (int j = tid; j < 512; j += 64){
        float v = fmaxf(g1[(long)row*512 + j] + bg1[j], 0.f);
        #pragma unroll
        for (int e = 0; e < 4; e++) a[e] = fmaf(v, Wg2[j*4+e], a[e]);
    }
    #pragma unroll
    for (int e = 0; e < 4; e++) red[e*64 + tid] = a[e];
    __syncthreads();
    for (int st = 32; st > 0; st >>= 1){
        if (tid < st){
            #pragma unroll
            for (int e = 0; e < 4; e++) red[e*64+tid] += red[e*64+tid+st];
        }
        __syncthreads();
    }
    if (tid == 0){
        float l[4]; for (int e = 0; e < 4; e++) l[e] = red[e*64];
        float m = fmaxf(fmaxf(l[0],l[1]), fmaxf(l[2],l[3]));
        float ex[4]; float s = 0.f;
        for (int e = 0; e < 4; e++){ ex[e] = expf(l[e]-m); s += ex[e]; }
        float gsv[4];
        for (int e = 0; e < 4; e++){ gsv[e] = ex[e]/s; gs[(long)row*4+e] = gsv[e]; }
        int i0 = 0;
        for (int e = 1; e < 4; e++) if (gsv[e] > gsv[i0]) i0 = e;
        int i1 = -1;
        for (int e = 0; e < 4; e++) if (e != i0 && (i1 < 0 || gsv[e] > gsv[i1])) i1 = e;
        float v0 = gsv[i0], v1 = gsv[i1];
        float mm = fmaxf(v0, v1);
        float w0 = expf(v0-mm), w1 = expf(v1-mm);
        float ws = w0 + w1;
        topi[row*2] = i0; topi[row*2+1] = i1;
        topw[row*2] = w0/ws; topw[row*2+1] = w1/ws;
    }
}

// ---------------- balance loss ----------------
__global__ void bal_k(const float* __restrict__ gs, float* __restrict__ out){
    int tid = threadIdx.x;
    __shared__ float red[256*4];
    float a[4] = {0.f,0.f,0.f,0.f};
    for (int r = tid; r < NTOK; r += 256){
        #pragma unroll
        for (int e = 0; e < 4; e++) a[e] += gs[(long)r*4+e];
    }
    #pragma unroll
    for (int e = 0; e < 4; e++) red[e*256+tid] = a[e];
    __syncthreads();
    for (int st = 128; st > 0; st >>= 1){
        if (tid < st){
            #pragma unroll
            for (int e = 0; e < 4; e++) red[e*256+tid] += red[e*256+tid+st];
        }
        __syncthreads();
    }
    if (tid == 0){
        float bal = 0.f;
        for (int e = 0; e < 4; e++){
            float gm = red[e*256] / (float)NTOK;
            bal += gm * logf(gm + 1e-8f);
        }
        out[0] = (float)NEXP * bal;
    }
}

// ---------------- MoE routing ----------------
__global__ void assign_k(const int* __restrict__ topi, int* __restrict__ cnt,
                         int* __restrict__ slot){
    int idx = blockIdx.x*256 + threadIdx.x;
    if (idx >= NTOK*2) return;
    int e = topi[idx];
    int s = atomicAdd(&cnt[e], 1);
    slot[idx] = e*NTOK + s;
}

__global__ void gather_k(const bf16* __restrict__ xf, const int* __restrict__ slot,
                         bf16* __restrict__ xg){
    int idx = blockIdx.x;
    int tok = idx >> 1;
    int dst = slot[idx];
    const unsigned* src = reinterpret_cast<const unsigned*>(xf) + (long)tok*(DM/2);
    unsigned* d = reinterpret_cast<unsigned*>(xg) + (long)dst*(DM/2);
    for (int i = threadIdx.x; i < DM/2; i += 128) d[i] = src[i];
}

// ---------------- MoE combine + final residual ----------------
__global__ void combine2_k(const float* __restrict__ x2, const float* __restrict__ ls3,
                           const bf16* __restrict__ eo, const int* __restrict__ slot,
                           const float* __restrict__ topw, float* __restrict__ out){
    long idx = (long)blockIdx.x*blockDim.x + threadIdx.x;
    if (idx >= (long)NTOK*DM) return;
    int row = (int)(idx / DM), d = (int)(idx % DM);
    int s0 = slot[row*2], s1 = slot[row*2+1];
    float m = topw[row*2]   * __bfloat162float(eo[(long)s0*DM + d])
            + topw[row*2+1] * __bfloat162float(eo[(long)s1*DM + d]);
    out[idx] = fmaf(ls3[d], m, x2[idx]);
}

// ============================== host ==============================
#define SYMPF(p, s) do { void* _t; cudaGetSymbolAddress(&_t, s); p = (float*)_t; } while(0)
#define SYMPB(p, s) do { void* _t; cudaGetSymbolAddress(&_t, s); p = (bf16*)_t; } while(0)
#define SYMPI(p, s) do { void* _t; cudaGetSymbolAddress(&_t, s); p = (int*)_t; } while(0)

extern "C" void kernel_launch(void* const* d_in, const int* in_sizes, int n_in,
                              void* d_out, int out_size){
    const float* x      = (const float*)d_in[0];
    const float* rms1_w = (const float*)d_in[1];
    const float* rms2_w = (const float*)d_in[2];
    const float* rms3_w = (const float*)d_in[3];
    const float* ls1    = (const float*)d_in[4];
    const float* ls2    = (const float*)d_in[5];
    const float* ls3    = (const float*)d_in[6];
    const float* W_in   = (const float*)d_in[7];
    const float* conv_w = (const float*)d_in[8];
    const float* conv_b = (const float*)d_in[9];
    const float* W_B    = (const float*)d_in[10];
    const float* W_C    = (const float*)d_in[11];
    const float* W_dt   = (const float*)d_in[12];
    const float* b_dt   = (const float*)d_in[13];
    const float* W_out_m= (const float*)d_in[14];
    const float* Avec   = (const float*)d_in[15];
    const float* Dp     = (const float*)d_in[16];
    const float* W_qkv  = (const float*)d_in[17];
    const float* W_o    = (const float*)d_in[18];
    const float* ascale = (const float*)d_in[19];
    const float* Wg1    = (const float*)d_in[20];
    const float* bg1    = (const float*)d_in[21];
    const float* Wg2    = (const float*)d_in[22];
    const float* w1     = (const float*)d_in[23];
    const float* w2     = (const float*)d_in[24];
    const float* w3     = (const float*)d_in[25];
    float* out = (float*)d_out;

    float *p_xz, *p_xc, *p_dtBC, *p_scanp, *p_x1, *p_x2, *p_g1, *p_gs, *p_topw;
    float *p_hend, *p_h0, *p_P;
    int *p_topi, *p_cnt, *p_slot;
    bf16 *b_rms1, *b_xc, *b_ymul, *b_rms2, *b_qkv, *b_q, *b_k, *b_v, *b_att, *b_xf,
         *b_xg, *b_h, *b_eo;
    bf16 *b_Win, *b_Wout, *b_Wqkv, *b_Wo, *b_Wg1, *b_w12, *b_w3, *b_Wcat;

    SYMPF(p_xz, g_xz); SYMPF(p_xc, g_xc); SYMPF(p_dtBC, g_dtBC); SYMPF(p_scanp, g_scanp);
    SYMPF(p_x1, g_x1);
    SYMPF(p_x2, g_x2); SYMPF(p_g1, g_g1); SYMPF(p_gs, g_gs); SYMPF(p_topw, g_topw);
    SYMPF(p_hend, g_hend); SYMPF(p_h0, g_h0); SYMPF(p_P, g_P);
    SYMPI(p_topi, g_topi); SYMPI(p_cnt, g_cnt); SYMPI(p_slot, g_slot);
    SYMPB(b_rms1, g_rms1b); SYMPB(b_xc, g_xcb); SYMPB(b_ymul, g_ymulb); SYMPB(b_rms2, g_rms2b);
    SYMPB(b_qkv, g_qkvb); SYMPB(b_q, g_qb); SYMPB(b_k, g_kb); SYMPB(b_v, g_vb);
    SYMPB(b_att, g_attb); SYMPB(b_xf, g_xfb); SYMPB(b_xg, g_xgb);
    SYMPB(b_h, g_hb); SYMPB(b_eo, g_eob);
    SYMPB(b_Win, g_Winb); SYMPB(b_Wout, g_Woutb); SYMPB(b_Wqkv, g_Wqkvb); SYMPB(b_Wo, g_Wob);
    SYMPB(b_Wg1, g_Wg1b); SYMPB(b_w12, g_w12b); SYMPB(b_w3, g_w3b); SYMPB(b_Wcat, g_Wcatb);

    cudaFuncSetAttribute(bgemm256_k<0,0>, cudaFuncAttributeMaxDynamicSharedMemorySize, DSMEM256);
    cudaFuncSetAttribute(bgemm256_k<2,0>, cudaFuncAttributeMaxDynamicSharedMemorySize, DSMEM256);
    cudaFuncSetAttribute(bgemm256_k<0,1>, cudaFuncAttributeMaxDynamicSharedMemorySize, DSMEM256);
    cudaFuncSetAttribute(bgemm256_k<3,1>, cudaFuncAttributeMaxDynamicSharedMemorySize, DSMEM256);
    cudaFuncSetAttribute(flash_k, cudaFuncAttributeMaxDynamicSharedMemorySize, FSMEM);

    // ---- weight conversions (merged) ----
    {
        long n0 = (long)DM*2*DI, n1 = (long)DI*DM, n2 = (long)DM*3*DM,
             n3 = (long)DM*DM, n4 = (long)DM*512, n5 = (long)NEXP*DFF*DM;
        long tot = n0+n1+n2+n3+n4+n5;
        convall_k<<<(int)((tot/4 + 255)/256), 256>>>(
            W_in, b_Win, n0,  W_out_m, b_Wout, n1,  W_qkv, b_Wqkv, n2,
            W_o,  b_Wo,  n3,  Wg1,     b_Wg1,  n4,  w3,    b_w3,   n5);
    }
    pack12_k<<<(int)(((long)NEXP*DM*DFF/4 + 255)/256), 256>>>(w1, w2, b_w12);
    packw_k<<<(DI*64+255)/256, 256>>>(W_dt, W_B, W_C, b_Wcat);

    // ---- 1. Mamba ----
    rmsnorm_bf_k<<<NTOK, 256>>>(x, rms1_w, b_rms1);
    {   dim3 g(2*DI/128, NTOK/256, 1);
        bgemm256_k<0,0><<<g, 256, DSMEM256>>>(b_rms1, b_Win, p_xz, NTOK, 2*DI, DM, DM, 2*DI, 2*DI,
                                              0,0,0, nullptr, nullptr, nullptr); }
    conv_k<<<(int)(((long)NTOK*DI/4+255)/256), 256>>>(p_xz, conv_w, conv_b, p_xc, b_xc);
    {   dim3 g(1, NTOK/128, 1);
        bgemm_k<<<g, 256>>>(b_xc, b_Wcat, p_dtBC, NTOK, 64, DI, DI, 64, 64); }
    scanprep_k<<<(NTOK*16+255)/256, 256>>>(p_dtBC, b_dt, Avec, p_scanp);
    {   dim3 g(16, NCH, BB);
        scanA_k<<<g, 128>>>(p_scanp, p_xc, p_hend, p_P); }
    scanComb_k<<<BB*DI/128, 128>>>(p_hend, p_P, p_h0);
    {   dim3 g(16, NCH, BB);
        scanC_k<<<g, 128>>>(p_scanp, p_xc, p_xz, Dp, p_h0, b_ymul); }
    {   dim3 g(DM/128, NTOK/256, 1);
        bgemm256_k<2,0><<<g, 256, DSMEM256>>>(b_ymul, b_Wout, p_x1, NTOK, DM, DI, DI, DM, DM,
                                              0,0,0, ls1, x, nullptr); }

    // ---- 2. Attention ----
    rmsnorm_bf_k<<<NTOK, 256>>>(p_x1, rms2_w, b_rms2);
    {   dim3 g(3*DM/128, NTOK/256, 1);
        bgemm256_k<0,1><<<g, 256, DSMEM256>>>(b_rms2, b_Wqkv, b_qkv, NTOK, 3*DM, DM, DM, 3*DM, 3*DM,
                                              0,0,0, nullptr, nullptr, nullptr); }
    rope2_k<<<NTOK, 256>>>(b_qkv, b_q, b_k, b_v);
    {   dim3 g(LSEQ/128, BB*NH, 1);
        flash_k<<<g, 256, FSMEM>>>(b_q, b_k, b_v, ascale, b_att); }
    {   dim3 g(DM/128, NTOK/256, 1);
        bgemm256_k<2,0><<<g, 256, DSMEM256>>>(b_att, b_Wo, p_x2, NTOK, DM, DM, DM, DM, DM,
                                              0,0,0, ls2, p_x1, nullptr); }

    // ---- 3. MoE (top-2 sparse) ----
    rmsnorm_bf_k<<<NTOK, 256>>>(p_x2, rms3_w, b_xf);
    {   dim3 g(512/128, NTOK/128, 1);
        bgemm_k<<<g, 256>>>(b_xf, b_Wg1, p_g1, NTOK, 512, DM, DM, 512, 512); }
    gate2_k<<<NTOK, 64>>>(p_g1, bg1, Wg2, p_gs, p_topi, p_topw, p_cnt);
    if (out_size > NTOK*DM)
        bal_k<<<1, 256>>>(p_gs, out + (long)NTOK*DM);
    assign_k<<<(NTOK*2+255)/256, 256>>>(p_topi, p_cnt, p_slot);
    gather_k<<<NTOK*2, 128>>>(b_xf, p_slot, b_xg);
    {   dim3 g12(2*DFF/128, NTOK/256, NEXP);
        bgemm256_k<3,1><<<g12, 256, DSMEM256>>>(b_xg, b_w12, b_h,
                                      NTOK, 2*DFF, DM, DM, 2*DFF, 2*DFF,
                                      (long)NTOK*DM, (long)DM*2*DFF, (long)NTOK*DFF,
                                      nullptr, nullptr, p_cnt);
    }
    {   dim3 g3(DM/128, NTOK/256, NEXP);
        bgemm256_k<0,1><<<g3, 256, DSMEM256>>>(b_h, b_w3, b_eo,
                                     NTOK, DM, DFF, DFF, DM, DM,
                                     (long)NTOK*DFF, (long)DFF*DM, (long)NTOK*DM,
                                     nullptr, nullptr, p_cnt);
    }
    combine2_k<<<(int)(((long)NTOK*DM+255)/256), 256>>>(p_x2, ls3, b_eo, p_slot, p_topw, out);
}

// round 17
// speedup vs baseline: 1.0147x; 1.0124x over previous
#include <cuda_runtime.h>
#include <cuda_bf16.h>
#include <math.h>

#define BB   2
#define LSEQ 2048
#define DM   1024
#define DI   2048
#define NH   8
#define DH   128
#define NEXP 4
#define DFF  4096
#define NTOK (BB*LSEQ)   // 4096
#define NCH  16
#define CLEN 128         // LSEQ/NCH
#define KSPL 4
#define KS   (DI/KSPL)   // 512

typedef __nv_bfloat16 bf16;

// ---------------- static scratch ----------------
__device__ float g_xz[NTOK*2*DI];
__device__ float g_xc[NTOK*DI];
__device__ float g_dtBC[NTOK*64];
__device__ float g_dtp[KSPL*NTOK*64];
__device__ float g_scanp[NTOK*48];
__device__ float g_x1[NTOK*DM];
__device__ float g_x2[NTOK*DM];
__device__ float g_g1[NTOK*512];
__device__ float g_gs[NTOK*NEXP];
__device__ int   g_topi[NTOK*2];
__device__ float g_topw[NTOK*2];
__device__ int   g_cnt[NEXP];
__device__ int   g_slot[NTOK*2];
__device__ float g_hend[BB*NCH*DI*16];
__device__ float g_h0[BB*NCH*DI*16];
__device__ float g_P[BB*NCH*16];

// bf16 activations
__device__ bf16 g_rms1b[NTOK*DM];
__device__ bf16 g_xcb[NTOK*DI];
__device__ bf16 g_ymulb[NTOK*DI];
__device__ bf16 g_rms2b[NTOK*DM];
__device__ bf16 g_qkvb[NTOK*3*DM];
__device__ bf16 g_qb[NTOK*DM];
__device__ bf16 g_kb[NTOK*DM];
__device__ bf16 g_vb[NTOK*DM];
__device__ bf16 g_attb[NTOK*DM];
__device__ bf16 g_xfb[NTOK*DM];
__device__ bf16 g_xgb[NEXP*NTOK*DM];
__device__ bf16 g_hb[(long)NEXP*NTOK*DFF];
__device__ bf16 g_eob[NEXP*NTOK*DM];

// bf16 weights
__device__ bf16 g_Winb[DM*2*DI];
__device__ bf16 g_Woutb[DI*DM];
__device__ bf16 g_Wqkvb[DM*3*DM];
__device__ bf16 g_Wob[DM*DM];
__device__ bf16 g_Wg1b[DM*512];
__device__ bf16 g_w12b[(long)NEXP*DM*2*DFF];
__device__ bf16 g_w3b[(long)NEXP*DFF*DM];
__device__ bf16 g_Wcatb[DI*64];

__device__ __forceinline__ float siluf(float x){ return x / (1.f + expf(-x)); }

// ---------------- merged fp32 -> bf16 conversions (6 segments) ----------------
__global__ void convall_k(const float* __restrict__ s0, bf16* __restrict__ d0, long n0,
                          const float* __restrict__ s1, bf16* __restrict__ d1, long n1,
                          const float* __restrict__ s2, bf16* __restrict__ d2, long n2,
                          const float* __restrict__ s3, bf16* __restrict__ d3, long n3,
                          const float* __restrict__ s4, bf16* __restrict__ d4, long n4,
                          const float* __restrict__ s5, bf16* __restrict__ d5, long n5){
    long i = ((long)blockIdx.x*blockDim.x + threadIdx.x)*4;
    const float* s; bf16* d;
    if (i < n0){ s = s0; d = d0; }
    else { i -= n0;
    if (i < n1){ s = s1; d = d1; }
    else { i -= n1;
    if (i < n2){ s = s2; d = d2; }
    else { i -= n2;
    if (i < n3){ s = s3; d = d3; }
    else { i -= n3;
    if (i < n4){ s = s4; d = d4; }
    else { i -= n4;
    if (i >= n5) return;
    s = s5; d = d5; }}}}}
    float4 v = *reinterpret_cast<const float4*>(s + i);
    *reinterpret_cast<__nv_bfloat162*>(d + i)     = __floats2bfloat162_rn(v.x, v.y);
    *reinterpret_cast<__nv_bfloat162*>(d + i + 2) = __floats2bfloat162_rn(v.z, v.w);
}

// pack w1|w2 INTERLEAVED
__global__ void pack12_k(const float* __restrict__ w1, const float* __restrict__ w2,
                         bf16* __restrict__ o){
    long i = ((long)blockIdx.x*blockDim.x + threadIdx.x)*4;
    if (i >= (long)NEXP*DM*DFF) return;
    long row = i >> 12;
    int  j   = (int)(i & 4095);
    float4 a = *reinterpret_cast<const float4*>(w1 + i);
    float4 b = *reinterpret_cast<const float4*>(w2 + i);
    bf16* d1 = o + row*(2*DFF) + 2*j;
    *reinterpret_cast<__nv_bfloat162*>(d1)   = __floats2bfloat162_rn(a.x, b.x);
    *reinterpret_cast<__nv_bfloat162*>(d1+2) = __floats2bfloat162_rn(a.y, b.y);
    *reinterpret_cast<__nv_bfloat162*>(d1+4) = __floats2bfloat162_rn(a.z, b.z);
    *reinterpret_cast<__nv_bfloat162*>(d1+6) = __floats2bfloat162_rn(a.w, b.w);
}

// pack [W_dt | W_B | W_C | 0] -> [2048][64] bf16
__global__ void packw_k(const float* __restrict__ Wdt, const float* __restrict__ WB,
                        const float* __restrict__ WC, bf16* __restrict__ o){
    int idx = blockIdx.x*256 + threadIdx.x;
    if (idx >= DI*64) return;
    int j = idx >> 6, n = idx & 63;
    float v = 0.f;
    if (n < 16) v = Wdt[j*16+n];
    else if (n < 32) v = WB[j*16+n-16];
    else if (n < 48) v = WC[j*16+n-32];
    o[idx] = __float2bfloat16(v);
}

// ---------------- RMSNorm -> bf16 (vectorized, warp reduce) ----------------
__global__ void rmsnorm_bf_k(const float* __restrict__ x, const float* __restrict__ w,
                             bf16* __restrict__ o){
    int row = blockIdx.x;
    int tid = threadIdx.x;
    const float* xr = x + (long)row*DM;
    float4 v = *reinterpret_cast<const float4*>(xr + tid*4);
    float s = v.x*v.x + v.y*v.y + v.z*v.z + v.w*v.w;
    #pragma unroll
    for (int off = 16; off > 0; off >>= 1)
        s += __shfl_xor_sync(0xffffffffu, s, off);
    __shared__ float red[8];
    if ((tid & 31) == 0) red[tid >> 5] = s;
    __syncthreads();
    float tot = red[0] + red[1] + red[2] + red[3]
              + red[4] + red[5] + red[6] + red[7];
    float r = rsqrtf(tot/(float)DM + 1e-6f);
    float4 wv = *reinterpret_cast<const float4*>(w + tid*4);
    bf16* ob = o + (long)row*DM + tid*4;
    *reinterpret_cast<__nv_bfloat162*>(ob)   = __floats2bfloat162_rn(wv.x*v.x*r, wv.y*v.y*r);
    *reinterpret_cast<__nv_bfloat162*>(ob+2) = __floats2bfloat162_rn(wv.z*v.z*r, wv.w*v.w*r);
}

// ---------------- MMA primitives ----------------
__device__ __forceinline__ void cpasync16(unsigned dst, const void* src, int ssz){
    asm volatile("cp.async.ca.shared.global [%0], [%1], 16, %2;"
        :: "r"(dst), "l"(src), "r"(ssz));
}
__device__ __forceinline__ void cp_commit(){ asm volatile("cp.async.commit_group;"); }
__device__ __forceinline__ void cp_wait0(){ asm volatile("cp.async.wait_group 0;"); }
__device__ __forceinline__ void cp_wait1(){ asm volatile("cp.async.wait_group 1;"); }
__device__ __forceinline__ void ldsm_x4(unsigned saddr, unsigned &o0, unsigned &o1,
                                        unsigned &o2, unsigned &o3){
    asm volatile("ldmatrix.sync.aligned.m8n8.x4.shared.b16 {%0,%1,%2,%3},[%4];"
        : "=r"(o0),"=r"(o1),"=r"(o2),"=r"(o3) : "r"(saddr));
}
__device__ __forceinline__ void ldsm_x4_t(unsigned saddr, unsigned &o0, unsigned &o1,
                                          unsigned &o2, unsigned &o3){
    asm volatile("ldmatrix.sync.aligned.m8n8.x4.trans.shared.b16 {%0,%1,%2,%3},[%4];"
        : "=r"(o0),"=r"(o1),"=r"(o2),"=r"(o3) : "r"(saddr));
}
__device__ __forceinline__ void mma16816(float* d, const unsigned* am, const unsigned* bm){
    asm volatile("mma.sync.aligned.m16n8k16.row.col.f32.bf16.bf16.f32 "
        "{%0,%1,%2,%3},{%4,%5,%6,%7},{%8,%9},{%0,%1,%2,%3};"
        : "+f"(d[0]),"+f"(d[1]),"+f"(d[2]),"+f"(d[3])
        : "r"(am[0]),"r"(am[1]),"r"(am[2]),"r"(am[3]), "r"(bm[0]),"r"(bm[1]));
}
__device__ __forceinline__ unsigned pkbf2(float x, float y){
    __nv_bfloat162 t = __floats2bfloat162_rn(x, y);
    return *reinterpret_cast<unsigned*>(&t);
}

// ---------------- 128x128 GEMM (fp32 out, optional split-K over blockIdx.z) ----------------
__device__ __forceinline__ void stage_tiles(const bf16* Ab, const bf16* Bb,
    int bm, int bn, int N, int lda, int ldb, int k0, int tid,
    unsigned Adst, unsigned Bdst)
{
    #pragma unroll
    for (int c = tid; c < 512; c += 256){
        int r  = c >> 2;
        int ko = (c & 3) << 3;
        cpasync16(Adst + 2u*(unsigned)(r*40 + ko),
                  Ab + (long)(bm + r)*lda + k0 + ko, 16);
    }
    #pragma unroll
    for (int c = tid; c < 512; c += 256){
        int r  = c >> 4;
        int no = (c & 15) << 3;
        const bf16* src = Bb + (long)(k0 + r)*ldb + bn + no;
        int ssz = 16;
        if (bn + no >= N){ src = Bb; ssz = 0; }
        cpasync16(Bdst + 2u*(unsigned)(r*136 + no), src, ssz);
    }
}

// KSPLIT=0: single-K kernel. KSPLIT=1: blockIdx.z selects K segment of length Kseg,
// partial written to Cv + z*M*ldc.
template<int KSPLIT>
__global__ void __launch_bounds__(256) bgemm_k(
    const bf16* __restrict__ Aptr, const bf16* __restrict__ Bptr, float* __restrict__ Cv,
    int M, int N, int K, int lda, int ldb, int ldc)
{
    __shared__ bf16 As[3*5120];
    __shared__ bf16 Bs[3*5120];
    const int bm = blockIdx.y * 128;
    const int bn = blockIdx.x * 128;
    const int tid  = threadIdx.x;
    const int lane = tid & 31;
    const int warp = tid >> 5;
    const int wm = warp >> 1;
    const int wn = warp & 1;

    const bf16* Ab = Aptr;
    const bf16* Bb = Bptr;
    float* Cb = Cv;
    if (KSPLIT){
        int z = blockIdx.z;
        Ab = Aptr + z*K;                      // column offset into A
        Bb = Bptr + (long)z*K*ldb;            // row offset into B
        Cb = Cv + (long)z*M*ldc;
    }

    float acc[2][8][4];
    #pragma unroll
    for (int i = 0; i < 2; i++)
        #pragma unroll
        for (int j = 0; j < 8; j++)
            #pragma unroll
            for (int q = 0; q < 4; q++) acc[i][j][q] = 0.f;

    unsigned Afrag[2][4];
    unsigned Bfrag[8][2];

    const unsigned As_base = (unsigned)__cvta_generic_to_shared(As);
    const unsigned Bs_base = (unsigned)__cvta_generic_to_shared(Bs);

    const int rowA = wm*32 + (lane & 15);
    const int colA = (lane >> 4) * 8;
    unsigned aoff0 = As_base + 2u*(unsigned)( rowA       *40 + colA);
    unsigned aoff1 = As_base + 2u*(unsigned)((rowA + 16) *40 + colA);

    unsigned boff[4];
    #pragma unroll
    for (int p = 0; p < 4; p++){
        int brow = lane & 15;
        int bcol = (lane >> 4) * 8;
        boff[p] = Bs_base + 2u*(unsigned)(brow*136 + wn*64 + p*16 + bcol);
    }

    const int nk = K >> 5;
    stage_tiles(Ab, Bb, bm, bn, N, lda, ldb, 0, tid, As_base, Bs_base);
    cp_commit();
    if (nk > 1){
        stage_tiles(Ab, Bb, bm, bn, N, lda, ldb, 32, tid,
                    As_base + 10240u, Bs_base + 10240u);
        cp_commit();
    }

    unsigned sb = 0u;
    for (int it = 0; it < nk; it++){
        if (it + 1 < nk) cp_wait1(); else cp_wait0();
        __syncthreads();
        if (it + 2 < nk){
            unsigned off = (unsigned)((it + 2) % 3) * 10240u;
            stage_tiles(Ab, Bb, bm, bn, N, lda, ldb, (it+2) << 5, tid,
                        As_base + off, Bs_base + off);
            cp_commit();
        }
        #pragma unroll
        for (int ks = 0; ks < 32; ks += 16){
            ldsm_x4(aoff0 + sb + 2u*ks, Afrag[0][0], Afrag[0][1], Afrag[0][2], Afrag[0][3]);
            ldsm_x4(aoff1 + sb + 2u*ks, Afrag[1][0], Afrag[1][1], Afrag[1][2], Afrag[1][3]);
            #pragma unroll
            for (int p = 0; p < 4; p++){
                unsigned ba = boff[p] + sb + 2u*(unsigned)(ks*136);
                ldsm_x4_t(ba, Bfrag[2*p][0], Bfrag[2*p][1],
                              Bfrag[2*p+1][0], Bfrag[2*p+1][1]);
            }
            #pragma unroll
            for (int mt = 0; mt < 2; mt++)
                #pragma unroll
                for (int nt = 0; nt < 8; nt++)
                    mma16816(acc[mt][nt], Afrag[mt], Bfrag[nt]);
        }
        sb += 10240u;
        if (sb == 30720u) sb = 0u;
    }

    #pragma unroll
    for (int mt = 0; mt < 2; mt++){
        int r0 = bm + wm*32 + mt*16 + (lane >> 2);
        #pragma unroll
        for (int nt = 0; nt < 8; nt++){
            int col = bn + wn*64 + nt*8 + ((lane & 3) << 1);
            if (col < N){
                *reinterpret_cast<float2*>(&Cb[(long)r0*ldc + col]) =
                    make_float2(acc[mt][nt][0], acc[mt][nt][1]);
                *reinterpret_cast<float2*>(&Cb[(long)(r0+8)*ldc + col]) =
                    make_float2(acc[mt][nt][2], acc[mt][nt][3]);
            }
        }
    }
}

// reduce 4 split-K partials (fixed order -> deterministic)
__global__ void reduce4_k(const float* __restrict__ p, float* __restrict__ o){
    long i = ((long)blockIdx.x*blockDim.x + threadIdx.x)*4;
    if (i >= (long)NTOK*64) return;
    float4 a = *reinterpret_cast<const float4*>(p + i);
    float4 b = *reinterpret_cast<const float4*>(p + (long)NTOK*64 + i);
    float4 c = *reinterpret_cast<const float4*>(p + 2L*NTOK*64 + i);
    float4 d = *reinterpret_cast<const float4*>(p + 3L*NTOK*64 + i);
    *reinterpret_cast<float4*>(o + i) =
        make_float4(((a.x + b.x) + c.x) + d.x, ((a.y + b.y) + c.y) + d.y,
                    ((a.z + b.z) + c.z) + d.z, ((a.w + b.w) + c.w) + d.w);
}

// ---------------- 256x128 GEMM, 3 slots x 64-K groups, dynamic smem ----------------
#define GSLOT_A 40960u
#define GSLOT_B 17408u
#define DSMEM256 (3*(GSLOT_A + GSLOT_B))

__device__ __forceinline__ void stage256(const bf16* Ab, const bf16* Bb,
    int bm, int bn, int N, int lda, int ldb, int k0, int tid,
    unsigned Adst, unsigned Bdst)
{
    #pragma unroll
    for (int c = tid; c < 1024; c += 256){
        int r  = c >> 2;
        int ko = (c & 3) << 3;
        cpasync16(Adst + 2u*(unsigned)(r*40 + ko),
                  Ab + (long)(bm + r)*lda + k0 + ko, 16);
    }
    #pragma unroll
    for (int c = tid; c < 512; c += 256){
        int r  = c >> 4;
        int no = (c & 15) << 3;
        const bf16* src = Bb + (long)(k0 + r)*ldb + bn + no;
        int ssz = 16;
        if (bn + no >= N){ src = Bb; ssz = 0; }
        cpasync16(Bdst + 2u*(unsigned)(r*136 + no), src, ssz);
    }
}

// EPI: 0 none, 1 relu(acc+bias) fp32, 2 resid fp32, 3 siluGLU bf16
template<int EPI, int OUTBF>
__global__ void __launch_bounds__(256) bgemm256_k(
    const bf16* __restrict__ Aptr, const bf16* __restrict__ Bptr, void* __restrict__ Cv,
    int M, int N, int K, int lda, int ldb, int ldc,
    long sA, long sB, long sC, const float* __restrict__ bias,
    const float* __restrict__ resx, const int* __restrict__ mcnt)
{
    extern __shared__ bf16 dsm[];
    const int bm = blockIdx.y * 256;
    int Meff = M;
    if (mcnt) Meff = mcnt[blockIdx.z];
    if (bm >= Meff) return;
    const bf16* Ab = Aptr + (long)blockIdx.z * sA;
    const bf16* Bb = Bptr + (long)blockIdx.z * sB;
    const int bn = blockIdx.x * 128;
    const int tid  = threadIdx.x;
    const int lane = tid & 31;
    const int warp = tid >> 5;
    const int wm = warp >> 1;
    const int wn = warp & 1;

    float acc[4][8][4];
    #pragma unroll
    for (int i = 0; i < 4; i++)
        #pragma unroll
        for (int j = 0; j < 8; j++)
            #pragma unroll
            for (int q = 0; q < 4; q++) acc[i][j][q] = 0.f;

    unsigned Afrag[4][4];
    unsigned Bfrag[8][2];

    const unsigned As_base = (unsigned)__cvta_generic_to_shared(dsm);
    const unsigned Bs_base = As_base + 3u*GSLOT_A;

    const int rowA = wm*64 + (lane & 15);
    const int colA = (lane >> 4) * 8;
    unsigned aoff[4];
    #pragma unroll
    for (int mt = 0; mt < 4; mt++)
        aoff[mt] = As_base + 2u*(unsigned)((rowA + mt*16)*40 + colA);

    unsigned boff[4];
    {
        int brow = lane & 15;
        int bcol = (lane >> 4) * 8;
        #pragma unroll
        for (int p = 0; p < 4; p++)
            boff[p] = Bs_base + 2u*(unsigned)(brow*136 + wn*64 + p*16 + bcol);
    }

    const int ng = K >> 6;
    stage256(Ab, Bb, bm, bn, N, lda, ldb, 0,  tid, As_base,           Bs_base);
    stage256(Ab, Bb, bm, bn, N, lda, ldb, 32, tid, As_base + 20480u,  Bs_base + 8704u);
    cp_commit();
    if (ng > 1){
        stage256(Ab, Bb, bm, bn, N, lda, ldb, 64, tid, As_base + GSLOT_A,           Bs_base + GSLOT_B);
        stage256(Ab, Bb, bm, bn, N, lda, ldb, 96, tid, As_base + GSLOT_A + 20480u,  Bs_base + GSLOT_B + 8704u);
        cp_commit();
    }

    for (int g = 0; g < ng; g++){
        if (g + 1 < ng) cp_wait1(); else cp_wait0();
        __syncthreads();
        if (g + 2 < ng){
            unsigned sl = (unsigned)((g + 2) % 3);
            int k0 = (g + 2) << 6;
            stage256(Ab, Bb, bm, bn, N, lda, ldb, k0,      tid,
                     As_base + sl*GSLOT_A,           Bs_base + sl*GSLOT_B);
            stage256(Ab, Bb, bm, bn, N, lda, ldb, k0 + 32, tid,
                     As_base + sl*GSLOT_A + 20480u,  Bs_base + sl*GSLOT_B + 8704u);
            cp_commit();
        }
        unsigned slA = (unsigned)(g % 3) * GSLOT_A;
        unsigned slB = (unsigned)(g % 3) * GSLOT_B;
        #pragma unroll
        for (int sub = 0; sub < 2; sub++){
            unsigned sa  = slA + (unsigned)sub*20480u;
            unsigned sbb = slB + (unsigned)sub*8704u;
            #pragma unroll
            for (int ks = 0; ks < 32; ks += 16){
                #pragma unroll
                for (int mt = 0; mt < 4; mt++)
                    ldsm_x4(aoff[mt] + sa + 2u*ks,
                            Afrag[mt][0], Afrag[mt][1], Afrag[mt][2], Afrag[mt][3]);
                #pragma unroll
                for (int p = 0; p < 4; p++){
                    unsigned ba = boff[p] + sbb + 2u*(unsigned)(ks*136);
                    ldsm_x4_t(ba, Bfrag[2*p][0], Bfrag[2*p][1],
                                  Bfrag[2*p+1][0], Bfrag[2*p+1][1]);
                }
                #pragma unroll
                for (int mt = 0; mt < 4; mt++)
                    #pragma unroll
                    for (int nt = 0; nt < 8; nt++)
                        mma16816(acc[mt][nt], Afrag[mt], Bfrag[nt]);
            }
        }
    }

    #pragma unroll
    for (int mt = 0; mt < 4; mt++){
        int r0 = bm + wm*64 + mt*16 + (lane >> 2);
        #pragma unroll
        for (int nt = 0; nt < 8; nt++){
            int col = bn + wn*64 + nt*8 + ((lane & 3) << 1);
            if (col < N){
                float v0 = acc[mt][nt][0];
                float v1 = acc[mt][nt][1];
                float v2 = acc[mt][nt][2];
                float v3 = acc[mt][nt][3];
                if (EPI == 3){
                    bf16* Cb = (bf16*)Cv + (long)blockIdx.z * sC;
                    int jc = col >> 1;
                    Cb[(long)r0*(N>>1) + jc]     = __float2bfloat16(siluf(v0)*v1);
                    Cb[(long)(r0+8)*(N>>1) + jc] = __float2bfloat16(siluf(v2)*v3);
                    continue;
                }
                if (EPI == 1){
                    float b0 = bias[col];
                    float b1 = bias[col+1];
                    v0 = fmaxf(v0+b0, 0.f); v1 = fmaxf(v1+b1, 0.f);
                    v2 = fmaxf(v2+b0, 0.f); v3 = fmaxf(v3+b1, 0.f);
                }
                if (EPI == 2){
                    float b0 = bias[col];
                    float b1 = bias[col+1];
                    v0 = fmaf(b0, v0, resx[(long)r0*ldc + col]);
                    v1 = fmaf(b1, v1, resx[(long)r0*ldc + col + 1]);
                    v2 = fmaf(b0, v2, resx[(long)(r0+8)*ldc + col]);
                    v3 = fmaf(b1, v3, resx[(long)(r0+8)*ldc + col + 1]);
                }
                if (OUTBF){
                    bf16* Cb = (bf16*)Cv + (long)blockIdx.z * sC;
                    *reinterpret_cast<__nv_bfloat162*>(&Cb[(long)r0*ldc + col]) =
                        __floats2bfloat162_rn(v0, v1);
                    *reinterpret_cast<__nv_bfloat162*>(&Cb[(long)(r0+8)*ldc + col]) =
                        __floats2bfloat162_rn(v2, v3);
                } else {
                    float* Cb = (float*)Cv + (long)blockIdx.z * sC;
                    *reinterpret_cast<float2*>(&Cb[(long)r0*ldc + col]) = make_float2(v0, v1);
                    *reinterpret_cast<float2*>(&Cb[(long)(r0+8)*ldc + col]) = make_float2(v2, v3);
                }
            }
        }
    }
}

// ---------------- fused flash attention ----------------
#define FTILE (128*136)
#define FSMEM (5*FTILE*2)

__device__ __forceinline__ void fstage(const bf16* src, unsigned dst, int tid){
    for (int i = tid; i < 2048; i += 256){
        int r = i >> 4, c = (i & 15) << 3;
        cpasync16(dst + 2u*(unsigned)(r*136 + c), src + r*DH + c, 16);
    }
}

__global__ void __launch_bounds__(256, 1) flash_k(
    const bf16* __restrict__ q, const bf16* __restrict__ k, const bf16* __restrict__ v,
    const float* __restrict__ ascale, bf16* __restrict__ att)
{
    extern __shared__ bf16 fs[];
    const int qt = blockIdx.x, bh = blockIdx.y;
    const int bb = bh >> 3, hh = bh & 7;
    const int tid = threadIdx.x, lane = tid & 31, w = tid >> 5;
    const float a = ascale[hh];

    const bf16* qg = q + ((long)bh*LSEQ + qt*128)*DH;
    const bf16* kg = k + (long)bh*LSEQ*DH;
    const bf16* vg = v + (long)bh*LSEQ*DH;

    const unsigned Qb = (unsigned)__cvta_generic_to_shared(fs);
    const unsigned Kb = Qb + 2u*FTILE;
    const unsigned Vb = Qb + 6u*FTILE;
    const unsigned TILEB = 2u*FTILE;

    fstage(qg, Qb, tid);
    fstage(kg, Kb, tid);
    fstage(vg, Vb, tid);
    cp_commit();
    cp_wait0();
    __syncthreads();

    unsigned qf[8][4];
    {
        int rq = w*16 + (lane & 15);
        int cq = (lane >> 4) << 3;
        #pragma unroll
        for (int ks = 0; ks < 8; ks++)
            ldsm_x4(Qb + 2u*(unsigned)(rq*136 + ks*16 + cq),
                    qf[ks][0], qf[ks][1], qf[ks][2], qf[ks][3]);
    }

    const int brow = (lane & 7) + (((lane >> 4) & 1) << 3);
    const int bcol = ((lane >> 3) & 1) << 3;
    unsigned kadr[8], vadr[8];
    #pragma unroll
    for (int p = 0; p < 8; p++){
        kadr[p] = Kb + 2u*(unsigned)((p*16 + brow)*136 + bcol);
        vadr[p] = Vb + 2u*(unsigned)((lane & 15)*136 + p*16 + ((lane >> 4) << 3));
    }

    float oacc[16][4];
    #pragma unroll
    for (int nt = 0; nt < 16; nt++)
        #pragma unroll
        for (int qq = 0; qq < 4; qq++) oacc[nt][qq] = 0.f;
    float m0 = -1e30f, m1 = -1e30f, l0 = 0.f, l1 = 0.f;

    for (int kt = 0; kt < 16; kt++){
        if (kt > 0){ cp_wait0(); __syncthreads(); }
        if (kt + 1 < 16){
            unsigned off = ((kt + 1) & 1) ? TILEB : 0u;
            fstage(kg + (long)(kt+1)*128*DH, Kb + off, tid);
            fstage(vg + (long)(kt+1)*128*DH, Vb + off, tid);
            cp_commit();
        }
        const unsigned sb = (kt & 1) ? TILEB : 0u;

        float sacc[16][4];
        #pragma unroll
        for (int nt = 0; nt < 16; nt++)
            #pragma unroll
            for (int qq = 0; qq < 4; qq++) sacc[nt][qq] = 0.f;

        #pragma unroll
        for (int ks = 0; ks < 8; ks++){
            #pragma unroll
            for (int p = 0; p < 8; p++){
                unsigned bf0[2], bf1[2];
                ldsm_x4(kadr[p] + sb + 2u*(unsigned)(ks*16),
                        bf0[0], bf0[1], bf1[0], bf1[1]);
                mma16816(sacc[2*p],   qf[ks], bf0);
                mma16816(sacc[2*p+1], qf[ks], bf1);
            }
        }

        float ax0 = -1e30f, ax1 = -1e30f;
        #pragma unroll
        for (int nt = 0; nt < 16; nt++){
            sacc[nt][0] *= a; sacc[nt][1] *= a; sacc[nt][2] *= a; sacc[nt][3] *= a;
            ax0 = fmaxf(ax0, fmaxf(sacc[nt][0], sacc[nt][1]));
            ax1 = fmaxf(ax1, fmaxf(sacc[nt][2], sacc[nt][3]));
        }
        ax0 = fmaxf(ax0, __shfl_xor_sync(0xffffffffu, ax0, 1));
        ax0 = fmaxf(ax0, __shfl_xor_sync(0xffffffffu, ax0, 2));
        ax1 = fmaxf(ax1, __shfl_xor_sync(0xffffffffu, ax1, 1));
        ax1 = fmaxf(ax1, __shfl_xor_sync(0xffffffffu, ax1, 2));
        float mn0 = fmaxf(m0, ax0), mn1 = fmaxf(m1, ax1);
        float f0 = expf(m0 - mn0), f1 = expf(m1 - mn1);

        float rs0 = 0.f, rs1 = 0.f;
        #pragma unroll
        for (int nt = 0; nt < 16; nt++){
            sacc[nt][0] = expf(sacc[nt][0] - mn0);
            sacc[nt][1] = expf(sacc[nt][1] - mn0);
            sacc[nt][2] = expf(sacc[nt][2] - mn1);
            sacc[nt][3] = expf(sacc[nt][3] - mn1);
            rs0 += sacc[nt][0] + sacc[nt][1];
            rs1 += sacc[nt][2] + sacc[nt][3];
        }
        rs0 += __shfl_xor_sync(0xffffffffu, rs0, 1);
        rs0 += __shfl_xor_sync(0xffffffffu, rs0, 2);
        rs1 += __shfl_xor_sync(0xffffffffu, rs1, 1);
        rs1 += __shfl_xor_sync(0xffffffffu, rs1, 2);
        l0 = l0*f0 + rs0; l1 = l1*f1 + rs1;
        m0 = mn0; m1 = mn1;

        #pragma unroll
        for (int nt = 0; nt < 16; nt++){
            oacc[nt][0] *= f0; oacc[nt][1] *= f0;
            oacc[nt][2] *= f1; oacc[nt][3] *= f1;
        }

        unsigned pa[8][4];
        #pragma unroll
        for (int ksp = 0; ksp < 8; ksp++){
            pa[ksp][0] = pkbf2(sacc[2*ksp][0],   sacc[2*ksp][1]);
            pa[ksp][1] = pkbf2(sacc[2*ksp][2],   sacc[2*ksp][3]);
            pa[ksp][2] = pkbf2(sacc[2*ksp+1][0], sacc[2*ksp+1][1]);
            pa[ksp][3] = pkbf2(sacc[2*ksp+1][2], sacc[2*ksp+1][3]);
        }

        #pragma unroll
        for (int ksp = 0; ksp < 8; ksp++){
            #pragma unroll
            for (int p = 0; p < 8; p++){
                unsigned bf0[2], bf1[2];
                ldsm_x4_t(vadr[p] + sb + 2u*(unsigned)(ksp*16*136),
                          bf0[0], bf0[1], bf1[0], bf1[1]);
                mma16816(oacc[2*p],   pa[ksp], bf0);
                mma16816(oacc[2*p+1], pa[ksp], bf1);
            }
        }
    }

    float inv0 = 1.f / l0, inv1 = 1.f / l1;
    long row0 = (long)bb*LSEQ + qt*128 + w*16 + (lane >> 2);
    long row1 = row0 + 8;
    int  cbase = hh*DH + ((lane & 3) << 1);
    #pragma unroll
    for (int nt = 0; nt < 16; nt++){
        int col = cbase + nt*8;
        *reinterpret_cast<__nv_bfloat162*>(&att[row0*DM + col]) =
            __floats2bfloat162_rn(oacc[nt][0]*inv0, oacc[nt][1]*inv0);
        *reinterpret_cast<__nv_bfloat162*>(&att[row1*DM + col]) =
            __floats2bfloat162_rn(oacc[nt][2]*inv1, oacc[nt][3]*inv1);
    }
}

// ---------------- depthwise conv + bias + SiLU (4-wide vectorized) ----------------
__global__ void conv_k(const float* __restrict__ xz, const float* __restrict__ cw,
                       const float* __restrict__ cb, float* __restrict__ xc,
                       bf16* __restrict__ xcb){
    long idx4 = (long)blockIdx.x*blockDim.x + threadIdx.x;
    if (idx4 >= (long)NTOK*DI/4) return;
    long idx = idx4 * 4;
    int d = (int)(idx % DI);
    int row = (int)(idx / DI);
    int t = row % LSEQ, b = row / LSEQ;
    float4 s = *reinterpret_cast<const float4*>(cb + d);
    float4 w0 = *reinterpret_cast<const float4*>(cw + d*4);
    float4 w1 = *reinterpret_cast<const float4*>(cw + (d+1)*4);
    float4 w2 = *reinterpret_cast<const float4*>(cw + (d+2)*4);
    float4 w3 = *reinterpret_cast<const float4*>(cw + (d+3)*4);
    const float* base = xz + (long)(b*LSEQ)*(2*DI) + d;
    #pragma unroll
    for (int k = 0; k < 4; k++){
        int tt = t + k - 2;
        if (tt >= 0 && tt < LSEQ){
            float4 xv = *reinterpret_cast<const float4*>(base + (long)tt*(2*DI));
            float wk0 = (k==0)?w0.x:(k==1)?w0.y:(k==2)?w0.z:w0.w;
            float wk1 = (k==0)?w1.x:(k==1)?w1.y:(k==2)?w1.z:w1.w;
            float wk2 = (k==0)?w2.x:(k==1)?w2.y:(k==2)?w2.z:w2.w;
            float wk3 = (k==0)?w3.x:(k==1)?w3.y:(k==2)?w3.z:w3.w;
            s.x = fmaf(wk0, xv.x, s.x);
            s.y = fmaf(wk1, xv.y, s.y);
            s.z = fmaf(wk2, xv.z, s.z);
            s.w = fmaf(wk3, xv.w, s.w);
        }
    }
    float4 v = make_float4(siluf(s.x), siluf(s.y), siluf(s.z), siluf(s.w));
    *reinterpret_cast<float4*>(xc + idx) = v;
    *reinterpret_cast<__nv_bfloat162*>(xcb + idx)     = __floats2bfloat162_rn(v.x, v.y);
    *reinterpret_cast<__nv_bfloat162*>(xcb + idx + 2) = __floats2bfloat162_rn(v.z, v.w);
}

// ---------------- scan preprocessing ----------------
__global__ void scanprep_k(const float* __restrict__ dtBC, const float* __restrict__ bdt,
                           const float* __restrict__ A, float* __restrict__ sp){
    int idx = blockIdx.x*blockDim.x + threadIdx.x;
    if (idx >= NTOK*16) return;
    int n = idx & 15, row = idx >> 4;
    float dtp = dtBC[(long)row*64 + n] + bdt[n];
    float dt  = fmaxf(dtp, 0.f) + log1pf(expf(-fabsf(dtp)));
    sp[(long)row*48 + n]      = expf(dt * A[n]);
    sp[(long)row*48 + 16 + n] = dt * dtBC[(long)row*64 + 16 + n];
    sp[(long)row*48 + 32 + n] = dtBC[(long)row*64 + 32 + n];
}

// ---------------- chunked selective scan (P folded into A) ----------------
__global__ void scanA_k(const float* __restrict__ sp, const float* __restrict__ xc,
                        float* __restrict__ hend, float* __restrict__ P){
    int b = blockIdx.z, ch = blockIdx.y;
    int d = blockIdx.x*128 + threadIdx.x;
    __shared__ float s[CLEN*48];
    const float* src = sp + ((long)b*LSEQ + ch*CLEN)*48;
    for (int i = threadIdx.x; i < CLEN*48; i += 128) s[i] = src[i];
    __syncthreads();
    if (blockIdx.x == 0 && threadIdx.x < 16){
        int n = threadIdx.x;
        float p = 1.f;
        for (int t = 0; t < CLEN; t++) p *= s[t*48 + n];
        P[(b*NCH + ch)*16 + n] = p;
    }
    float h[16];
    #pragma unroll
    for (int n = 0; n < 16; n++) h[n] = 0.f;
    long rowbase = (long)b*LSEQ + ch*CLEN;
    float xv_next = xc[rowbase*DI + d];
    for (int tt = 0; tt < CLEN; tt++){
        float xv = xv_next;
        if (tt + 1 < CLEN) xv_next = xc[(rowbase + tt + 1)*DI + d];
        const float* e = s + tt*48;
        #pragma unroll
        for (int n = 0; n < 16; n++)
            h[n] = fmaf(e[n], h[n], e[16+n]*xv);
    }
    float* o = hend + (((long)(b*NCH + ch)*DI + d) << 4);
    #pragma unroll
    for (int n = 0; n < 16; n += 4)
        *reinterpret_cast<float4*>(o + n) = make_float4(h[n], h[n+1], h[n+2], h[n+3]);
}

__global__ void scanComb_k(const float* __restrict__ hend, const float* __restrict__ P,
                           float* __restrict__ h0){
    int g = blockIdx.x*128 + threadIdx.x;
    int b = g / DI, d = g % DI;
    __shared__ float sP[NCH*16];
    for (int i = threadIdx.x; i < NCH*16; i += 128) sP[i] = P[b*NCH*16 + i];
    __syncthreads();
    float h[16];
    #pragma unroll
    for (int n = 0; n < 16; n++) h[n] = 0.f;
    {
        float* o = h0 + (((long)(b*NCH)*DI + d) << 4);
        #pragma unroll
        for (int n = 0; n < 16; n += 4)
            *reinterpret_cast<float4*>(o + n) = make_float4(0.f, 0.f, 0.f, 0.f);
    }
    for (int c = 1; c < NCH; c++){
        const float* he = hend + (((long)(b*NCH + c - 1)*DI + d) << 4);
        #pragma unroll
        for (int n = 0; n < 16; n++)
            h[n] = fmaf(sP[(c-1)*16 + n], h[n], he[n]);
        float* o = h0 + (((long)(b*NCH + c)*DI + d) << 4);
        #pragma unroll
        for (int n = 0; n < 16; n += 4)
            *reinterpret_cast<float4*>(o + n) = make_float4(h[n], h[n+1], h[n+2], h[n+3]);
    }
}

__global__ void scanC_k(const float* __restrict__ sp, const float* __restrict__ xc,
                        const float* __restrict__ xz, const float* __restrict__ Dp,
                        const float* __restrict__ h0, bf16* __restrict__ ymulb){
    int b = blockIdx.z, ch = blockIdx.y;
    int d = blockIdx.x*128 + threadIdx.x;
    __shared__ float s[CLEN*48];
    const float* src = sp + ((long)b*LSEQ + ch*CLEN)*48;
    for (int i = threadIdx.x; i < CLEN*48; i += 128) s[i] = src[i];
    __syncthreads();
    float h[16];
    {   const float* hi = h0 + (((long)(b*NCH + ch)*DI + d) << 4);
        #pragma unroll
        for (int n = 0; n < 16; n += 4){
            float4 v = *reinterpret_cast<const float4*>(hi + n);
            h[n] = v.x; h[n+1] = v.y; h[n+2] = v.z; h[n+3] = v.w;
        }
    }
    const float dpv = Dp[d];
    long rowbase = (long)b*LSEQ + ch*CLEN;
    float xv_next = xc[rowbase*DI + d];
    float z_next  = xz[rowbase*(2*DI) + DI + d];
    for (int tt = 0; tt < CLEN; tt++){
        float xv = xv_next;
        float z  = z_next;
        if (tt + 1 < CLEN){
            xv_next = xc[(rowbase + tt + 1)*DI + d];
            z_next  = xz[(rowbase + tt + 1)*(2*DI) + DI + d];
        }
        const float* e = s + tt*48;
        float y = 0.f;
        #pragma unroll
        for (int n = 0; n < 16; n++){
            h[n] = fmaf(e[n], h[n], e[16+n]*xv);
            y = fmaf(h[n], e[32+n], y);
        }
        ymulb[(rowbase + tt)*DI + d] = __float2bfloat16((y + dpv*xv) * siluf(z));
    }
}

// ---------------- RoPE (bf16 qkv in) -> qb,kb,vb bf16 ----------------
__global__ void rope2_k(const bf16* __restrict__ qkv, bf16* __restrict__ qb,
                        bf16* __restrict__ kb, bf16* __restrict__ vb){
    int row = blockIdx.x;
    int t = row % LSEQ, b = row / LSEQ;
    __shared__ float q[DM], kk[DM];
    const bf16* base = qkv + (long)row*3*DM;
    for (int i = threadIdx.x; i < DM; i += 256){
        q[i]  = __bfloat162float(base[i]);
        kk[i] = __bfloat162float(base[DM+i]);
    }
    __syncthreads();
    const float sq = sqrtf((float)DH);
    const float lg = logf(10000.f) / 64.f;
    for (int idx = threadIdx.x; idx < DM; idx += 256){
        int h = idx / DH, i = idx % DH;
        int j = i & 63;
        float inv = expf(-(float)j * lg);
        float ang = (float)t * inv;
        float c = cosf(ang), s = sinf(ang);
        int off = h * DH;
        float rq, rk;
        if (i < 64){ rq = -q[off + 2*i + 1]; rk = -kk[off + 2*i + 1]; }
        else       { rq =  q[off + 2*(i-64)]; rk =  kk[off + 2*(i-64)]; }
        long o = ((long)(b*NH + h)*LSEQ + t)*DH + i;
        qb[o] = __float2bfloat16((q[idx]*c + rq*s) * sq);
        kb[o] = __float2bfloat16(kk[idx]*c + rk*s);
        vb[o] = base[2*DM + idx];
    }
}

// ---------------- gate stage 2 (bias+relu folded in; zeroes counters) ----------------
__global__ void gate2_k(const float* __restrict__ g1, const float* __restrict__ bg1,
                        const float* __restrict__ Wg2,
                        float* __restrict__ gs, int* __restrict__ topi, float* __restrict__ topw,
                        int* __restrict__ cnt){
    int row = blockIdx.x;
    int tid = threadIdx.x;
    if (row == 0 && tid < NEXP) cnt[tid] = 0;
    __shared__ float red[64*4];
    float a[4] = {0.f,0.f,0.f,0.f};
    for (int j = tid; j < 512; j += 64){
        float v = fmaxf(g1[(long)row*512 + j] + bg1[j], 0.f);
        #pragma unroll
        for (int e = 0; e < 4; e++) a[e] = fmaf(v, Wg2[j*4+e], a[e]);
    }
    #pragma unroll
    for (int e = 0; e < 4; e++) red[e*64 + tid] = a[e];
    __syncthreads();
    for (int st = 32; st > 0; st >>= 1){
        if (tid < st){
            #pragma unroll
            for (int e = 0; e < 4; e++) red[e*64+tid] += red[e*64+tid+st];
        }
        __syncthreads();
    }
    if (tid == 0){
        float l[4]; for (int e = 0; e < 4; e++) l[e] = red[e*64];
        float m = fmaxf(fmaxf(l[0],l[1]), fmaxf(l[2],l[3]));
        float ex[4]; float s = 0.f;
        for (int e = 0; e < 4; e++){ ex[e] = expf(l[e]-m); s += ex[e]; }
        float gsv[4];
        for (int e = 0; e < 4; e++){ gsv[e] = ex[e]/s; gs[(long)row*4+e] = gsv[e]; }
        int i0 = 0;
        for (int e = 1; e < 4; e++) if (gsv[e] > gsv[i0]) i0 = e;
        int i1 = -1;
        for (int e = 0; e < 4; e++) if (e != i0 && (i1 < 0 || gsv[e] > gsv[i1])) i1 = e;
        float v0 = gsv[i0], v1 = gsv[i1];
        float mm = fmaxf(v0, v1);
        float w0 = expf(v0-mm), w1 = expf(v1-mm);
        float ws = w0 + w1;
        topi[row*2] = i0; topi[row*2+1] = i1;
        topw[row*2] = w0/ws; topw[row*2+1] = w1/ws;
    }
}

// ---------------- balance loss ----------------
__global__ void bal_k(const float* __restrict__ gs, float* __restrict__ out){
    int tid = threadIdx.x;
    __shared__ float red[256*4];
    float a[4] = {0.f,0.f,0.f,0.f};
    for (int r = tid; r < NTOK; r += 256){
        #pragma unroll
        for (int e = 0; e < 4; e++) a[e] += gs[(long)r*4+e];
    }
    #pragma unroll
    for (int e = 0; e < 4; e++) red[e*256+tid] = a[e];
    __syncthreads();
    for (int st = 128; st > 0; st >>= 1){
        if (tid < st){
            #pragma unroll
            for (int e = 0; e < 4; e++) red[e*256+tid] += red[e*256+tid+st];
        }
        __syncthreads();
    }
    if (tid == 0){
        float bal = 0.f;
        for (int e = 0; e < 4; e++){
            float gm = red[e*256] / (float)NTOK;
            bal += gm * logf(gm + 1e-8f);
        }
        out[0] = (float)NEXP * bal;
    }
}

// ---------------- MoE routing ----------------
__global__ void assign_k(const int* __restrict__ topi, int* __restrict__ cnt,
                         int* __restrict__ slot){
    int idx = blockIdx.x*256 + threadIdx.x;
    if (idx >= NTOK*2) return;
    int e = topi[idx];
    int s = atomicAdd(&cnt[e], 1);
    slot[idx] = e*NTOK + s;
}

__global__ void gather_k(const bf16* __restrict__ xf, const int* __restrict__ slot,
                         bf16* __restrict__ xg){
    int idx = blockIdx.x;
    int tok = idx >> 1;
    int dst = slot[idx];
    const unsigned* src = reinterpret_cast<const unsigned*>(xf) + (long)tok*(DM/2);
    unsigned* d = reinterpret_cast<unsigned*>(xg) + (long)dst*(DM/2);
    for (int i = threadIdx.x; i < DM/2; i += 128) d[i] = src[i];
}

// ---------------- MoE combine + final residual (2-wide vectorized) ----------------
__global__ void combine2_k(const float* __restrict__ x2, const float* __restrict__ ls3,
                           const bf16* __restrict__ eo, const int* __restrict__ slot,
                           const float* __restrict__ topw, float* __restrict__ out){
    long idx2 = (long)blockIdx.x*blockDim.x + threadIdx.x;
    if (idx2 >= (long)NTOK*DM/2) return;
    int row = (int)(idx2 / (DM/2));
    int d   = (int)(idx2 % (DM/2)) * 2;
    long base = (long)row*DM + d;
    int s0 = slot[row*2], s1 = slot[row*2+1];
    float w0 = topw[row*2], w1 = topw[row*2+1];
    __nv_bfloat162 e0 = *reinterpret_cast<const __nv_bfloat162*>(&eo[(long)s0*DM + d]);
    __nv_bfloat162 e1 = *reinterpret_cast<const __nv_bfloat162*>(&eo[(long)s1*DM + d]);
    float2 l = *reinterpret_cast<const float2*>(&ls3[d]);
    float2 xv = *reinterpret_cast<const float2*>(&x2[base]);
    float m0 = w0*__bfloat162float(e0.x) + w1*__bfloat162float(e1.x);
    float m1 = w0*__bfloat162float(e0.y) + w1*__bfloat162float(e1.y);
    *reinterpret_cast<float2*>(&out[base]) =
        make_float2(fmaf(l.x, m0, xv.x), fmaf(l.y, m1, xv.y));
}

// ============================== host ==============================
#define SYMPF(p, s) do { void* _t; cudaGetSymbolAddress(&_t, s); p = (float*)_t; } while(0)
#define SYMPB(p, s) do { void* _t; cudaGetSymbolAddress(&_t, s); p = (bf16*)_t; } while(0)
#define SYMPI(p, s) do { void* _t; cudaGetSymbolAddress(&_t, s); p = (int*)_t; } while(0)

extern "C" void kernel_launch(void* const* d_in, const int* in_sizes, int n_in,
                              void* d_out, int out_size){
    const float* x      = (const float*)d_in[0];
    const float* rms1_w = (const float*)d_in[1];
    const float* rms2_w = (const float*)d_in[2];
    const float* rms3_w = (const float*)d_in[3];
    const float* ls1    = (const float*)d_in[4];
    const float* ls2    = (const float*)d_in[5];
    const float* ls3    = (const float*)d_in[6];
    const float* W_in   = (const float*)d_in[7];
    const float* conv_w = (const float*)d_in[8];
    const float* conv_b = (const float*)d_in[9];
    const float* W_B    = (const float*)d_in[10];
    const float* W_C    = (const float*)d_in[11];
    const float* W_dt   = (const float*)d_in[12];
    const float* b_dt   = (const float*)d_in[13];
    const float* W_out_m= (const float*)d_in[14];
    const float* Avec   = (const float*)d_in[15];
    const float* Dp     = (const float*)d_in[16];
    const float* W_qkv  = (const float*)d_in[17];
    const float* W_o    = (const float*)d_in[18];
    const float* ascale = (const float*)d_in[19];
    const float* Wg1    = (const float*)d_in[20];
    const float* bg1    = (const float*)d_in[21];
    const float* Wg2    = (const float*)d_in[22];
    const float* w1     = (const float*)d_in[23];
    const float* w2     = (const float*)d_in[24];
    const float* w3     = (const float*)d_in[25];
    float* out = (float*)d_out;

    float *p_xz, *p_xc, *p_dtBC, *p_dtp, *p_scanp, *p_x1, *p_x2, *p_g1, *p_gs, *p_topw;
    float *p_hend, *p_h0, *p_P;
    int *p_topi, *p_cnt, *p_slot;
    bf16 *b_rms1, *b_xc, *b_ymul, *b_rms2, *b_qkv, *b_q, *b_k, *b_v, *b_att, *b_xf,
         *b_xg, *b_h, *b_eo;
    bf16 *b_Win, *b_Wout, *b_Wqkv, *b_Wo, *b_Wg1, *b_w12, *b_w3, *b_Wcat;

    SYMPF(p_xz, g_xz); SYMPF(p_xc, g_xc); SYMPF(p_dtBC, g_dtBC); SYMPF(p_dtp, g_dtp);
    SYMPF(p_scanp, g_scanp); SYMPF(p_x1, g_x1);
    SYMPF(p_x2, g_x2); SYMPF(p_g1, g_g1); SYMPF(p_gs, g_gs); SYMPF(p_topw, g_topw);
    SYMPF(p_hend, g_hend); SYMPF(p_h0, g_h0); SYMPF(p_P, g_P);
    SYMPI(p_topi, g_topi); SYMPI(p_cnt, g_cnt); SYMPI(p_slot, g_slot);
    SYMPB(b_rms1, g_rms1b); SYMPB(b_xc, g_xcb); SYMPB(b_ymul, g_ymulb); SYMPB(b_rms2, g_rms2b);
    SYMPB(b_qkv, g_qkvb); SYMPB(b_q, g_qb); SYMPB(b_k, g_kb); SYMPB(b_v, g_vb);
    SYMPB(b_att, g_attb); SYMPB(b_xf, g_xfb); SYMPB(b_xg, g_xgb);
    SYMPB(b_h, g_hb); SYMPB(b_eo, g_eob);
    SYMPB(b_Win, g_Winb); SYMPB(b_Wout, g_Woutb); SYMPB(b_Wqkv, g_Wqkvb); SYMPB(b_Wo, g_Wob);
    SYMPB(b_Wg1, g_Wg1b); SYMPB(b_w12, g_w12b); SYMPB(b_w3, g_w3b); SYMPB(b_Wcat, g_Wcatb);

    cudaFuncSetAttribute(bgemm256_k<0,0>, cudaFuncAttributeMaxDynamicSharedMemorySize, DSMEM256);
    cudaFuncSetAttribute(bgemm256_k<2,0>, cudaFuncAttributeMaxDynamicSharedMemorySize, DSMEM256);
    cudaFuncSetAttribute(bgemm256_k<0,1>, cudaFuncAttributeMaxDynamicSharedMemorySize, DSMEM256);
    cudaFuncSetAttribute(bgemm256_k<3,1>, cudaFuncAttributeMaxDynamicSharedMemorySize, DSMEM256);
    cudaFuncSetAttribute(flash_k, cudaFuncAttributeMaxDynamicSharedMemorySize, FSMEM);

    // ---- weight conversions (merged) ----
    {
        long n0 = (long)DM*2*DI, n1 = (long)DI*DM, n2 = (long)DM*3*DM,
             n3 = (long)DM*DM, n4 = (long)DM*512, n5 = (long)NEXP*DFF*DM;
        long tot = n0+n1+n2+n3+n4+n5;
        convall_k<<<(int)((tot/4 + 255)/256), 256>>>(
            W_in, b_Win, n0,  W_out_m, b_Wout, n1,  W_qkv, b_Wqkv, n2,
            W_o,  b_Wo,  n3,  Wg1,     b_Wg1,  n4,  w3,    b_w3,   n5);
    }
    pack12_k<<<(int)(((long)NEXP*DM*DFF/4 + 255)/256), 256>>>(w1, w2, b_w12);
    packw_k<<<(DI*64+255)/256, 256>>>(W_dt, W_B, W_C, b_Wcat);

    // ---- 1. Mamba ----
    rmsnorm_bf_k<<<NTOK, 256>>>(x, rms1_w, b_rms1);
    {   dim3 g(2*DI/128, NTOK/256, 1);
        bgemm256_k<0,0><<<g, 256, DSMEM256>>>(b_rms1, b_Win, p_xz, NTOK, 2*DI, DM, DM, 2*DI, 2*DI,
                                              0,0,0, nullptr, nullptr, nullptr); }
    conv_k<<<(int)(((long)NTOK*DI/4+255)/256), 256>>>(p_xz, conv_w, conv_b, p_xc, b_xc);
    {   // dtBC GEMM: split-K x4 over blockIdx.z (128 CTAs instead of 32)
        dim3 g(1, NTOK/128, KSPL);
        bgemm_k<1><<<g, 256>>>(b_xc, b_Wcat, p_dtp, NTOK, 64, KS, DI, 64, 64); }
    reduce4_k<<<(NTOK*64/4+255)/256, 256>>>(p_dtp, p_dtBC);
    scanprep_k<<<(NTOK*16+255)/256, 256>>>(p_dtBC, b_dt, Avec, p_scanp);
    {   dim3 g(16, NCH, BB);
        scanA_k<<<g, 128>>>(p_scanp, p_xc, p_hend, p_P); }
    scanComb_k<<<BB*DI/128, 128>>>(p_hend, p_P, p_h0);
    {   dim3 g(16, NCH, BB);
        scanC_k<<<g, 128>>>(p_scanp, p_xc, p_xz, Dp, p_h0, b_ymul); }
    {   dim3 g(DM/128, NTOK/256, 1);
        bgemm256_k<2,0><<<g, 256, DSMEM256>>>(b_ymul, b_Wout, p_x1, NTOK, DM, DI, DI, DM, DM,
                                              0,0,0, ls1, x, nullptr); }

    // ---- 2. Attention ----
    rmsnorm_bf_k<<<NTOK, 256>>>(p_x1, rms2_w, b_rms2);
    {   dim3 g(3*DM/128, NTOK/256, 1);
        bgemm256_k<0,1><<<g, 256, DSMEM256>>>(b_rms2, b_Wqkv, b_qkv, NTOK, 3*DM, DM, DM, 3*DM, 3*DM,
                                              0,0,0, nullptr, nullptr, nullptr); }
    rope2_k<<<NTOK, 256>>>(b_qkv, b_q, b_k, b_v);
    {   dim3 g(LSEQ/128, BB*NH, 1);
        flash_k<<<g, 256, FSMEM>>>(b_q, b_k, b_v, ascale, b_att); }
    {   dim3 g(DM/128, NTOK/256, 1);
        bgemm256_k<2,0><<<g, 256, DSMEM256>>>(b_att, b_Wo, p_x2, NTOK, DM, DM, DM, DM, DM,
                                              0,0,0, ls2, p_x1, nullptr); }

    // ---- 3. MoE (top-2 sparse) ----
    rmsnorm_bf_k<<<NTOK, 256>>>(p_x2, rms3_w, b_xf);
    {   dim3 g(512/128, NTOK/128, 1);
        bgemm_k<0><<<g, 256>>>(b_xf, b_Wg1, p_g1, NTOK, 512, DM, DM, 512, 512); }
    gate2_k<<<NTOK, 64>>>(p_g1, bg1, Wg2, p_gs, p_topi, p_topw, p_cnt);
    if (out_size > NTOK*DM)
        bal_k<<<1, 256>>>(p_gs, out + (long)NTOK*DM);
    assign_k<<<(NTOK*2+255)/256, 256>>>(p_topi, p_cnt, p_slot);
    gather_k<<<NTOK*2, 128>>>(b_xf, p_slot, b_xg);
    {   dim3 g12(2*DFF/128, NTOK/256, NEXP);
        bgemm256_k<3,1><<<g12, 256, DSMEM256>>>(b_xg, b_w12, b_h,
                                      NTOK, 2*DFF, DM, DM, 2*DFF, 2*DFF,
                                      (long)NTOK*DM, (long)DM*2*DFF, (long)NTOK*DFF,
                                      nullptr, nullptr, p_cnt);
    }
    {   dim3 g3(DM/128, NTOK/256, NEXP);
        bgemm256_k<0,1><<<g3, 256, DSMEM256>>>(b_h, b_w3, b_eo,
                                     NTOK, DM, DFF, DFF, DM, DM,
                                     (long)NTOK*DFF, (long)DFF*DM, (long)NTOK*DM,
                                     nullptr, nullptr, p_cnt);
    }
    combine2_k<<<(int)(((long)NTOK*DM/2+255)/256), 256>>>(p_x2, ls3, b_eo, p_slot, p_topw, out);
}